// round 7
// baseline (speedup 1.0000x reference)
#include <cuda_runtime.h>
#include <cstdint>

#define NN 100000
#define NE 1600000
#define SCAN_B 256
#define NBLK ((NN + SCAN_B - 1) / SCAN_B)   // 391

// ---- static device scratch (no allocation allowed) ----
__device__ __align__(16) float g_dinv[NN];
__device__ __align__(16) int   g_src[NE];
__device__ __align__(16) int   g_dst[NE];
__device__ __align__(16) int   g_col[NE];
__device__ __align__(16) int   g_rowptr[NN + 1];
__device__ __align__(16) int   g_deg[NN];
__device__ __align__(16) int   g_scan[NN];
__device__ __align__(16) int   g_cursor[NN];
__device__ __align__(16) int   g_bsum[NBLK];
__device__ __align__(16) int   g_boff[NBLK];
__device__ __align__(16) float g_hs [12800000];   // N x 128 max
__device__ __align__(16) float g_act[12800000];
__device__ int g_is64;

// ---------------- dtype sniff ----------------
__global__ void k_sniff(const unsigned int* __restrict__ w) {
    if (threadIdx.x == 0 && blockIdx.x == 0) {
        int is64 = 1;
        for (int i = 0; i < 128; i++)
            if (w[2 * i + 1] != 0u) { is64 = 0; break; }
        g_is64 = is64;
    }
}

// ---------------- CSR build ----------------
__global__ void k_zero_deg() {
    int i = blockIdx.x * blockDim.x + threadIdx.x;
    if (i < NN) g_deg[i] = 0;
}

__global__ void k_prep_edges(const void* __restrict__ ei) {
    int e = blockIdx.x * blockDim.x + threadIdx.x;
    if (e >= NE) return;
    long long s, d;
    if (g_is64) {
        const long long* p = (const long long*)ei;
        s = p[e]; d = p[NE + e];
    } else {
        const int* p = (const int*)ei;
        s = p[e]; d = p[NE + e];
    }
    if (s >= 0 && s < NN && d >= 0 && d < NN) {
        g_src[e] = (int)s;
        g_dst[e] = (int)d;
        atomicAdd(&g_deg[(int)d], 1);
    } else {
        g_src[e] = -1;   // sentinel
        g_dst[e] = 0;
    }
}

__global__ void k_scan1() {
    __shared__ int sm[SCAN_B];
    int tid = threadIdx.x;
    int i = blockIdx.x * SCAN_B + tid;
    sm[tid] = (i < NN) ? g_deg[i] : 0;
    __syncthreads();
#pragma unroll
    for (int off = 1; off < SCAN_B; off <<= 1) {
        int t = (tid >= off) ? sm[tid - off] : 0;
        __syncthreads();
        if (tid >= off) sm[tid] += t;
        __syncthreads();
    }
    if (i < NN) g_scan[i] = sm[tid];
    if (tid == SCAN_B - 1) g_bsum[blockIdx.x] = sm[SCAN_B - 1];
}

__global__ void k_scan2() {
    __shared__ int sm[512];
    int tid = threadIdx.x;
    sm[tid] = (tid < NBLK) ? g_bsum[tid] : 0;
    __syncthreads();
#pragma unroll
    for (int off = 1; off < 512; off <<= 1) {
        int t = (tid >= off) ? sm[tid - off] : 0;
        __syncthreads();
        if (tid >= off) sm[tid] += t;
        __syncthreads();
    }
    if (tid < NBLK) g_boff[tid] = sm[tid] - g_bsum[tid];   // exclusive
}

__global__ void k_finalize_csr() {
    int i = blockIdx.x * blockDim.x + threadIdx.x;
    if (i >= NN) return;
    int incl = g_scan[i] + g_boff[i / SCAN_B];
    int deg = g_deg[i];
    g_rowptr[i] = incl - deg;
    g_cursor[i] = 0;
    g_dinv[i] = rsqrtf((float)deg + 1.0f);
    if (i == NN - 1) g_rowptr[NN] = incl;
}

__global__ void k_fill() {
    int e = blockIdx.x * blockDim.x + threadIdx.x;
    if (e >= NE) return;
    int s = g_src[e];
    if (s < 0) return;
    int d = g_dst[e];
    int pos = g_rowptr[d] + atomicAdd(&g_cursor[d], 1);
    g_col[pos] = s;
}

// -------- GEMM layer-1 half: 128 rows x 64 cols per block, BK=16 --------
// 256 threads, 8x4 per-thread tile, double-buffered. Writes RAW h to
// g_hs[row*128 + c0 + col].
__global__ __launch_bounds__(256) void gemm128h(const float* __restrict__ in,
                                                const float* __restrict__ W,
                                                int c0) {
    __shared__ __align__(16) float xs[2][16][136];   // k-major, padded
    __shared__ __align__(16) float ws[2][16][64];
    int tid = threadIdx.x;
    int tx = tid & 15, ty = tid >> 4;   // tx: 16 x 4 cols, ty: 16 x 8 rows
    int rowBase = blockIdx.x * 128;
    float acc[8][4];
#pragma unroll
    for (int i = 0; i < 8; i++)
#pragma unroll
        for (int j = 0; j < 4; j++) acc[i][j] = 0.0f;

    // prologue: tile 0
#pragma unroll
    for (int i = 0; i < 8; i++) {
        int idx = tid + i * 256;
        int m = idx >> 4, c = idx & 15;
        int gr = rowBase + m;
        xs[0][c][m] = (gr < NN) ? in[gr * 128 + c] : 0.0f;
    }
#pragma unroll
    for (int i = 0; i < 4; i++) {
        int idx = tid + i * 256;
        int k = idx >> 6, j = idx & 63;
        ws[0][k][j] = W[k * 128 + c0 + j];
    }
    __syncthreads();

    for (int kt = 0; kt < 8; kt++) {
        int buf = kt & 1;
        if (kt < 7) {
            int k0 = (kt + 1) * 16;
            int nb = buf ^ 1;
#pragma unroll
            for (int i = 0; i < 8; i++) {
                int idx = tid + i * 256;
                int m = idx >> 4, c = idx & 15;
                int gr = rowBase + m;
                xs[nb][c][m] = (gr < NN) ? in[gr * 128 + k0 + c] : 0.0f;
            }
#pragma unroll
            for (int i = 0; i < 4; i++) {
                int idx = tid + i * 256;
                int k = idx >> 6, j = idx & 63;
                ws[nb][k][j] = W[(k0 + k) * 128 + c0 + j];
            }
        }
#pragma unroll
        for (int k = 0; k < 16; k++) {
            float rm[8], rn[4];
            *(float4*)&rm[0] = *(const float4*)&xs[buf][k][ty * 8];
            *(float4*)&rm[4] = *(const float4*)&xs[buf][k][ty * 8 + 4];
            *(float4*)&rn[0] = *(const float4*)&ws[buf][k][tx * 4];
#pragma unroll
            for (int i = 0; i < 8; i++)
#pragma unroll
                for (int j = 0; j < 4; j++)
                    acc[i][j] = fmaf(rm[i], rn[j], acc[i][j]);
        }
        __syncthreads();
    }

#pragma unroll
    for (int i = 0; i < 8; i++) {
        int row = rowBase + ty * 8 + i;
        if (row < NN) {
            float4 v;
            v.x = acc[i][0]; v.y = acc[i][1];
            v.z = acc[i][2]; v.w = acc[i][3];
            *(float4*)&g_hs[row * 128 + c0 + tx * 4] = v;
        }
    }
}

// -------- small GEMM half: one thread per row, FH cols starting at c0 ------
template <int FIN, int FOUT, int FH>
__global__ __launch_bounds__(256) void gemm_small_h(const float* __restrict__ in,
                                                    const float* __restrict__ W,
                                                    int c0) {
    __shared__ float ws[FIN * FH];
    __shared__ float xs[256][9];    // BK=8, padded
    int tid = threadIdx.x;
    for (int i = tid; i < FIN * FH; i += 256) {
        int k = i / FH, j = i - k * FH;
        ws[i] = W[k * FOUT + c0 + j];
    }

    int rowBase = blockIdx.x * 256;
    int row = rowBase + tid;
    float acc[FH];
#pragma unroll
    for (int j = 0; j < FH; j++) acc[j] = 0.0f;

    for (int k0 = 0; k0 < FIN; k0 += 8) {
#pragma unroll
        for (int i = 0; i < 8; i++) {
            int idx = tid + i * 256;
            int r = idx >> 3, c = idx & 7;
            int gr = rowBase + r;
            xs[r][c] = (gr < NN) ? in[gr * FIN + k0 + c] : 0.0f;
        }
        __syncthreads();
#pragma unroll
        for (int k = 0; k < 8; k++) {
            float xv = xs[tid][k];
            const float* wrow = &ws[(k0 + k) * FH];
#pragma unroll
            for (int j = 0; j < FH; j++)
                acc[j] = fmaf(xv, wrow[j], acc[j]);
        }
        __syncthreads();
    }

    if (row < NN) {
#pragma unroll
        for (int j = 0; j < FH; j += 4) {
            float4 v;
            v.x = acc[j + 0];
            v.y = acc[j + 1];
            v.z = acc[j + 2];
            v.w = acc[j + 3];
            *(float4*)&g_hs[row * FOUT + c0 + j] = v;
        }
    }
}

// ---- fused aggregate + norm + bias + relu over FH cols at offset c0 ----
// h is RAW; out[n] = relu(dinv[n]*(dinv[n]*h[n] + sum_s dinv[s]*h[s]) + b)
template <int F, int FH>
__global__ __launch_bounds__(256) void aggregate_h(const float* __restrict__ bias,
                                                   float* __restrict__ outp,
                                                   int c0) {
    constexpr int L = FH / 4;       // lanes per node
    constexpr int NPW = 32 / L;     // nodes per warp
    int warp = (blockIdx.x * 256 + threadIdx.x) >> 5;
    int lane = threadIdx.x & 31;
    int node = warp * NPW + lane / L;
    int cc = c0 + (lane % L) * 4;
    if (node >= NN) return;

    float dvn = g_dinv[node];
    int beg = g_rowptr[node];
    int end = g_rowptr[node + 1];
    float4 hv = *(const float4*)&g_hs[(size_t)node * F + cc];
    float4 acc;
    acc.x = dvn * hv.x; acc.y = dvn * hv.y;
    acc.z = dvn * hv.z; acc.w = dvn * hv.w;

    int e = beg;
    for (; e + 1 < end; e += 2) {
        int s0 = g_col[e];
        int s1 = g_col[e + 1];
        float d0 = g_dinv[s0];
        float d1 = g_dinv[s1];
        float4 v0 = *(const float4*)&g_hs[(size_t)s0 * F + cc];
        float4 v1 = *(const float4*)&g_hs[(size_t)s1 * F + cc];
        acc.x = fmaf(d0, v0.x, fmaf(d1, v1.x, acc.x));
        acc.y = fmaf(d0, v0.y, fmaf(d1, v1.y, acc.y));
        acc.z = fmaf(d0, v0.z, fmaf(d1, v1.z, acc.z));
        acc.w = fmaf(d0, v0.w, fmaf(d1, v1.w, acc.w));
    }
    if (e < end) {
        int s = g_col[e];
        float ds = g_dinv[s];
        float4 v = *(const float4*)&g_hs[(size_t)s * F + cc];
        acc.x = fmaf(ds, v.x, acc.x);
        acc.y = fmaf(ds, v.y, acc.y);
        acc.z = fmaf(ds, v.z, acc.z);
        acc.w = fmaf(ds, v.w, acc.w);
    }

    float4 b = *(const float4*)&bias[cc];
    float4 r;
    r.x = fmaxf(fmaf(dvn, acc.x, b.x), 0.0f);
    r.y = fmaxf(fmaf(dvn, acc.y, b.y), 0.0f);
    r.z = fmaxf(fmaf(dvn, acc.z, b.z), 0.0f);
    r.w = fmaxf(fmaf(dvn, acc.w, b.w), 0.0f);
    *(float4*)&outp[(size_t)node * F + cc] = r;
}

template <int FH>
static inline int aggh_blocks() {
    int npw = 32 / (FH / 4);
    int nodes_per_block = npw * 8;
    return (NN + nodes_per_block - 1) / nodes_per_block;
}

// ---------------- launch ----------------
extern "C" void kernel_launch(void* const* d_in, const int* in_sizes, int n_in,
                              void* d_out, int out_size) {
    const float* x  = (const float*)d_in[0];
    const void*  ei = d_in[1];
    const float* W1 = (const float*)d_in[2];
    const float* b1 = (const float*)d_in[3];
    const float* W2 = (const float*)d_in[4];
    const float* b2 = (const float*)d_in[5];
    const float* W3 = (const float*)d_in[6];
    const float* b3 = (const float*)d_in[7];
    const float* W4 = (const float*)d_in[8];
    const float* b4 = (const float*)d_in[9];
    const float* W5 = (const float*)d_in[10];
    const float* b5 = (const float*)d_in[11];
    float* out = (float*)d_out;

    static float* act = nullptr;
    static cudaStream_t s1 = nullptr;
    static cudaEvent_t ev0 = nullptr, evP = nullptr, ev1a = nullptr,
                       evA1a = nullptr, ev2a = nullptr, evA2a = nullptr;
    if (!act) {
        cudaGetSymbolAddress((void**)&act, g_act);
        cudaStreamCreateWithFlags(&s1, cudaStreamNonBlocking);
        cudaEventCreateWithFlags(&ev0,   cudaEventDisableTiming);
        cudaEventCreateWithFlags(&evP,   cudaEventDisableTiming);
        cudaEventCreateWithFlags(&ev1a,  cudaEventDisableTiming);
        cudaEventCreateWithFlags(&evA1a, cudaEventDisableTiming);
        cudaEventCreateWithFlags(&ev2a,  cudaEventDisableTiming);
        cudaEventCreateWithFlags(&evA2a, cudaEventDisableTiming);
    }

    int nb = (NN + 255) / 256;
    int eb = (NE + 255) / 256;
    int gt = (NN + 127) / 128;

    // fork: CSR build on s1, layer-1 GEMM halves on main stream
    cudaEventRecord(ev0, 0);
    cudaStreamWaitEvent(s1, ev0, 0);

    k_sniff        <<<1, 32, 0, s1>>>((const unsigned int*)ei);
    k_zero_deg     <<<nb, 256, 0, s1>>>();
    k_prep_edges   <<<eb, 256, 0, s1>>>(ei);
    k_scan1        <<<NBLK, SCAN_B, 0, s1>>>();
    k_scan2        <<<1, 512, 0, s1>>>();
    k_finalize_csr <<<nb, 256, 0, s1>>>();
    k_fill         <<<eb, 256, 0, s1>>>();
    cudaEventRecord(evP, s1);

    // ---- layer 1: split into col halves, pipeline G/A across streams ----
    gemm128h<<<gt, 256>>>(x, W1, 0);
    cudaEventRecord(ev1a, 0);
    gemm128h<<<gt, 256>>>(x, W1, 64);

    cudaStreamWaitEvent(s1, ev1a, 0);   // s1: prep done (program order) + G1a
    aggregate_h<128, 64><<<aggh_blocks<64>(), 256, 0, s1>>>(b1, act, 0);
    cudaEventRecord(evA1a, s1);

    cudaStreamWaitEvent(0, evP, 0);     // s0: CSR ready for A1b
    aggregate_h<128, 64><<<aggh_blocks<64>(), 256>>>(b1, act, 64);

    // ---- layer 2: 128 -> 64, split into 32-col halves ----
    cudaStreamWaitEvent(0, evA1a, 0);   // act fully written
    gemm_small_h<128, 64, 32><<<nb, 256>>>(act, W2, 0);
    cudaEventRecord(ev2a, 0);
    gemm_small_h<128, 64, 32><<<nb, 256>>>(act, W2, 32);

    cudaStreamWaitEvent(s1, ev2a, 0);
    aggregate_h<64, 32><<<aggh_blocks<32>(), 256, 0, s1>>>(b2, act, 0);
    cudaEventRecord(evA2a, s1);

    aggregate_h<64, 32><<<aggh_blocks<32>(), 256>>>(b2, act, 32);

    // ---- layers 3-5 sequential on s0 ----
    cudaStreamWaitEvent(0, evA2a, 0);
    gemm_small_h<64, 32, 32><<<nb, 256>>>(act, W3, 0);
    aggregate_h<32, 32><<<aggh_blocks<32>(), 256>>>(b3, act, 0);

    gemm_small_h<32, 16, 16><<<nb, 256>>>(act, W4, 0);
    aggregate_h<16, 16><<<aggh_blocks<16>(), 256>>>(b4, act, 0);

    gemm_small_h<16, 8, 8><<<nb, 256>>>(act, W5, 0);
    aggregate_h<8, 8><<<aggh_blocks<8>(), 256>>>(b5, out, 0);
}

// round 8
// speedup vs baseline: 1.1817x; 1.1817x over previous
#include <cuda_runtime.h>
#include <cuda_fp16.h>
#include <cstdint>

#define NN 100000
#define NE 1600000
#define SCAN_B 256
#define NBLK ((NN + SCAN_B - 1) / SCAN_B)   // 391

// ---- static device scratch (no allocation allowed) ----
__device__ __align__(16) float  g_dinv[NN];
__device__ __align__(16) int    g_src[NE];
__device__ __align__(16) int    g_dst[NE];
__device__ __align__(16) int    g_col[NE];
__device__ __align__(16) int    g_rowptr[NN + 1];
__device__ __align__(16) int    g_deg[NN];
__device__ __align__(16) int    g_scan[NN];
__device__ __align__(16) int    g_cursor[NN];
__device__ __align__(16) int    g_bsum[NBLK];
__device__ __align__(16) int    g_boff[NBLK];
__device__ __align__(16) __half g_hsh[12800000];  // N x 128 max, fp16
__device__ __align__(16) float  g_act[12800000];
__device__ int g_is64;

// ---------------- dtype sniff ----------------
__global__ void k_sniff(const unsigned int* __restrict__ w) {
    if (threadIdx.x == 0 && blockIdx.x == 0) {
        int is64 = 1;
        for (int i = 0; i < 128; i++)
            if (w[2 * i + 1] != 0u) { is64 = 0; break; }
        g_is64 = is64;
    }
}

// ---------------- CSR build ----------------
__global__ void k_zero_deg() {
    int i = blockIdx.x * blockDim.x + threadIdx.x;
    if (i < NN) g_deg[i] = 0;
}

__global__ void k_prep_edges(const void* __restrict__ ei) {
    int e = blockIdx.x * blockDim.x + threadIdx.x;
    if (e >= NE) return;
    long long s, d;
    if (g_is64) {
        const long long* p = (const long long*)ei;
        s = p[e]; d = p[NE + e];
    } else {
        const int* p = (const int*)ei;
        s = p[e]; d = p[NE + e];
    }
    if (s >= 0 && s < NN && d >= 0 && d < NN) {
        g_src[e] = (int)s;
        g_dst[e] = (int)d;
        atomicAdd(&g_deg[(int)d], 1);
    } else {
        g_src[e] = -1;   // sentinel
        g_dst[e] = 0;
    }
}

__global__ void k_scan1() {
    __shared__ int sm[SCAN_B];
    int tid = threadIdx.x;
    int i = blockIdx.x * SCAN_B + tid;
    sm[tid] = (i < NN) ? g_deg[i] : 0;
    __syncthreads();
#pragma unroll
    for (int off = 1; off < SCAN_B; off <<= 1) {
        int t = (tid >= off) ? sm[tid - off] : 0;
        __syncthreads();
        if (tid >= off) sm[tid] += t;
        __syncthreads();
    }
    if (i < NN) g_scan[i] = sm[tid];
    if (tid == SCAN_B - 1) g_bsum[blockIdx.x] = sm[SCAN_B - 1];
}

__global__ void k_scan2() {
    __shared__ int sm[512];
    int tid = threadIdx.x;
    sm[tid] = (tid < NBLK) ? g_bsum[tid] : 0;
    __syncthreads();
#pragma unroll
    for (int off = 1; off < 512; off <<= 1) {
        int t = (tid >= off) ? sm[tid - off] : 0;
        __syncthreads();
        if (tid >= off) sm[tid] += t;
        __syncthreads();
    }
    if (tid < NBLK) g_boff[tid] = sm[tid] - g_bsum[tid];   // exclusive
}

__global__ void k_finalize_csr() {
    int i = blockIdx.x * blockDim.x + threadIdx.x;
    if (i >= NN) return;
    int incl = g_scan[i] + g_boff[i / SCAN_B];
    int deg = g_deg[i];
    g_rowptr[i] = incl - deg;
    g_cursor[i] = 0;
    g_dinv[i] = rsqrtf((float)deg + 1.0f);
    if (i == NN - 1) g_rowptr[NN] = incl;
}

__global__ void k_fill() {
    int e = blockIdx.x * blockDim.x + threadIdx.x;
    if (e >= NE) return;
    int s = g_src[e];
    if (s < 0) return;
    int d = g_dst[e];
    int pos = g_rowptr[d] + atomicAdd(&g_cursor[d], 1);
    g_col[pos] = s;
}

// ---------------- GEMM, layer 1 (128x128), double-buffered ----------------
// Writes RAW h in fp16 (dinv deferred to aggregate1, preserving prep overlap).
__global__ __launch_bounds__(256) void gemm128(const float* __restrict__ in,
                                               const float* __restrict__ W) {
    __shared__ __align__(16) float xs[2][16][136];   // k-major, padded
    __shared__ __align__(16) float ws[2][16][128];
    int tid = threadIdx.x;
    int tx = tid & 15, ty = tid >> 4;
    int rowBase = blockIdx.x * 128;
    float acc[8][8];
#pragma unroll
    for (int i = 0; i < 8; i++)
#pragma unroll
        for (int j = 0; j < 8; j++) acc[i][j] = 0.0f;

    // prologue
#pragma unroll
    for (int i = 0; i < 8; i++) {
        int idx = tid + i * 256;
        int m = idx >> 4, c = idx & 15;
        int gr = rowBase + m;
        xs[0][c][m] = (gr < NN) ? in[gr * 128 + c] : 0.0f;
    }
#pragma unroll
    for (int i = 0; i < 8; i++) {
        int idx = tid + i * 256;
        int k = idx >> 7, j = idx & 127;
        ws[0][k][j] = W[k * 128 + j];
    }
    __syncthreads();

    for (int kt = 0; kt < 8; kt++) {
        int buf = kt & 1;
        if (kt < 7) {
            int k0 = (kt + 1) * 16;
            int nb = buf ^ 1;
#pragma unroll
            for (int i = 0; i < 8; i++) {
                int idx = tid + i * 256;
                int m = idx >> 4, c = idx & 15;
                int gr = rowBase + m;
                xs[nb][c][m] = (gr < NN) ? in[gr * 128 + k0 + c] : 0.0f;
            }
#pragma unroll
            for (int i = 0; i < 8; i++) {
                int idx = tid + i * 256;
                int k = idx >> 7, j = idx & 127;
                ws[nb][k][j] = W[(k0 + k) * 128 + j];
            }
        }
#pragma unroll
        for (int k = 0; k < 16; k++) {
            float rm[8], rn[8];
            *(float4*)&rm[0] = *(const float4*)&xs[buf][k][ty * 8];
            *(float4*)&rm[4] = *(const float4*)&xs[buf][k][ty * 8 + 4];
            *(float4*)&rn[0] = *(const float4*)&ws[buf][k][tx * 8];
            *(float4*)&rn[4] = *(const float4*)&ws[buf][k][tx * 8 + 4];
#pragma unroll
            for (int i = 0; i < 8; i++)
#pragma unroll
                for (int j = 0; j < 8; j++)
                    acc[i][j] = fmaf(rm[i], rn[j], acc[i][j]);
        }
        __syncthreads();
    }

#pragma unroll
    for (int i = 0; i < 8; i++) {
        int row = rowBase + ty * 8 + i;
        if (row < NN) {
            __half2 ph[4];
#pragma unroll
            for (int j = 0; j < 4; j++)
                ph[j] = __floats2half2_rn(acc[i][2 * j], acc[i][2 * j + 1]);
            *(uint4*)&g_hsh[(size_t)row * 128 + tx * 8] = *(uint4*)ph;
        }
    }
}

// ---------------- GEMM, layers 2-5 (FOUT <= 64) ----------------
// Writes hs = dinv[row] * h in fp16.
template <int FIN, int FOUT>
__global__ __launch_bounds__(256) void gemm_small(const float* __restrict__ in,
                                                  const float* __restrict__ W) {
    __shared__ float ws[FIN * FOUT];
    __shared__ float xs[256][9];    // BK=8, padded
    int tid = threadIdx.x;
    for (int i = tid; i < FIN * FOUT; i += 256) ws[i] = W[i];

    int rowBase = blockIdx.x * 256;
    int row = rowBase + tid;
    float acc[FOUT];
#pragma unroll
    for (int j = 0; j < FOUT; j++) acc[j] = 0.0f;

    for (int k0 = 0; k0 < FIN; k0 += 8) {
#pragma unroll
        for (int i = 0; i < 8; i++) {
            int idx = tid + i * 256;
            int r = idx >> 3, c = idx & 7;
            int gr = rowBase + r;
            xs[r][c] = (gr < NN) ? in[gr * FIN + k0 + c] : 0.0f;
        }
        __syncthreads();
#pragma unroll
        for (int k = 0; k < 8; k++) {
            float xv = xs[tid][k];
            const float* wrow = &ws[(k0 + k) * FOUT];
#pragma unroll
            for (int j = 0; j < FOUT; j++)
                acc[j] = fmaf(xv, wrow[j], acc[j]);
        }
        __syncthreads();
    }

    if (row < NN) {
        float dv = g_dinv[row];
#pragma unroll
        for (int j = 0; j < FOUT; j += 8) {
            __half2 ph[4];
#pragma unroll
            for (int q = 0; q < 4; q++)
                ph[q] = __floats2half2_rn(acc[j + 2 * q] * dv,
                                          acc[j + 2 * q + 1] * dv);
            *(uint4*)&g_hsh[(size_t)row * FOUT + j] = *(uint4*)ph;
        }
    }
}

// ---- aggregate layer 1: raw fp16 h, per-edge dinv ----
// out[n] = relu(dinv[n]*(dinv[n]*h[n] + sum_s dinv[s]*h[s]) + b)
__global__ __launch_bounds__(256) void aggregate1(const float* __restrict__ bias,
                                                  float* __restrict__ outp) {
    constexpr int F = 128;
    constexpr int L = 16;           // lanes per node (8 halfs each)
    int warp = (blockIdx.x * 256 + threadIdx.x) >> 5;
    int lane = threadIdx.x & 31;
    int node = warp * 2 + (lane >> 4);
    int c8 = (lane & 15) * 8;
    if (node >= NN) return;
    (void)L;

    float dvn = g_dinv[node];
    int beg = g_rowptr[node];
    int end = g_rowptr[node + 1];

    float a[8];
    {
        uint4 raw = *(const uint4*)&g_hsh[(size_t)node * F + c8];
        const __half2* hp = (const __half2*)&raw;
#pragma unroll
        for (int q = 0; q < 4; q++) {
            float2 f = __half22float2(hp[q]);
            a[2 * q]     = dvn * f.x;
            a[2 * q + 1] = dvn * f.y;
        }
    }

    int e = beg;
    for (; e + 1 < end; e += 2) {
        int s0 = g_col[e];
        int s1 = g_col[e + 1];
        float d0 = g_dinv[s0];
        float d1 = g_dinv[s1];
        uint4 r0 = *(const uint4*)&g_hsh[(size_t)s0 * F + c8];
        uint4 r1 = *(const uint4*)&g_hsh[(size_t)s1 * F + c8];
        const __half2* h0 = (const __half2*)&r0;
        const __half2* h1 = (const __half2*)&r1;
#pragma unroll
        for (int q = 0; q < 4; q++) {
            float2 f0 = __half22float2(h0[q]);
            float2 f1 = __half22float2(h1[q]);
            a[2 * q]     = fmaf(d0, f0.x, fmaf(d1, f1.x, a[2 * q]));
            a[2 * q + 1] = fmaf(d0, f0.y, fmaf(d1, f1.y, a[2 * q + 1]));
        }
    }
    if (e < end) {
        int s = g_col[e];
        float ds = g_dinv[s];
        uint4 r = *(const uint4*)&g_hsh[(size_t)s * F + c8];
        const __half2* h = (const __half2*)&r;
#pragma unroll
        for (int q = 0; q < 4; q++) {
            float2 f = __half22float2(h[q]);
            a[2 * q]     = fmaf(ds, f.x, a[2 * q]);
            a[2 * q + 1] = fmaf(ds, f.y, a[2 * q + 1]);
        }
    }

    float4 b0 = *(const float4*)&bias[c8];
    float4 b1 = *(const float4*)&bias[c8 + 4];
    float4 o0, o1;
    o0.x = fmaxf(fmaf(dvn, a[0], b0.x), 0.0f);
    o0.y = fmaxf(fmaf(dvn, a[1], b0.y), 0.0f);
    o0.z = fmaxf(fmaf(dvn, a[2], b0.z), 0.0f);
    o0.w = fmaxf(fmaf(dvn, a[3], b0.w), 0.0f);
    o1.x = fmaxf(fmaf(dvn, a[4], b1.x), 0.0f);
    o1.y = fmaxf(fmaf(dvn, a[5], b1.y), 0.0f);
    o1.z = fmaxf(fmaf(dvn, a[6], b1.z), 0.0f);
    o1.w = fmaxf(fmaf(dvn, a[7], b1.w), 0.0f);
    *(float4*)&outp[(size_t)node * F + c8]     = o0;
    *(float4*)&outp[(size_t)node * F + c8 + 4] = o1;
}

// ---- aggregate layers 2-5: hs already pre-scaled by dinv[src] ----
// out[n] = relu(dinv[n]*(hs[n] + sum_s hs[s]) + b)
template <int F>
__global__ __launch_bounds__(256) void aggregate2(const float* __restrict__ bias,
                                                  float* __restrict__ outp) {
    constexpr int L = F / 8;        // lanes per node (8 halfs each)
    constexpr int NPW = 32 / L;     // nodes per warp
    int warp = (blockIdx.x * 256 + threadIdx.x) >> 5;
    int lane = threadIdx.x & 31;
    int node = warp * NPW + lane / L;
    int c8 = (lane % L) * 8;
    if (node >= NN) return;

    float dvn = g_dinv[node];
    int beg = g_rowptr[node];
    int end = g_rowptr[node + 1];

    float a[8];
    {
        uint4 raw = *(const uint4*)&g_hsh[(size_t)node * F + c8];
        const __half2* hp = (const __half2*)&raw;
#pragma unroll
        for (int q = 0; q < 4; q++) {
            float2 f = __half22float2(hp[q]);
            a[2 * q] = f.x;
            a[2 * q + 1] = f.y;
        }
    }

    int e = beg;
    for (; e + 1 < end; e += 2) {
        int s0 = g_col[e];
        int s1 = g_col[e + 1];
        uint4 r0 = *(const uint4*)&g_hsh[(size_t)s0 * F + c8];
        uint4 r1 = *(const uint4*)&g_hsh[(size_t)s1 * F + c8];
        const __half2* h0 = (const __half2*)&r0;
        const __half2* h1 = (const __half2*)&r1;
#pragma unroll
        for (int q = 0; q < 4; q++) {
            float2 f0 = __half22float2(h0[q]);
            float2 f1 = __half22float2(h1[q]);
            a[2 * q]     += f0.x + f1.x;
            a[2 * q + 1] += f0.y + f1.y;
        }
    }
    if (e < end) {
        int s = g_col[e];
        uint4 r = *(const uint4*)&g_hsh[(size_t)s * F + c8];
        const __half2* h = (const __half2*)&r;
#pragma unroll
        for (int q = 0; q < 4; q++) {
            float2 f = __half22float2(h[q]);
            a[2 * q]     += f.x;
            a[2 * q + 1] += f.y;
        }
    }

    float4 b0 = *(const float4*)&bias[c8];
    float4 b1 = *(const float4*)&bias[c8 + 4];
    float4 o0, o1;
    o0.x = fmaxf(fmaf(dvn, a[0], b0.x), 0.0f);
    o0.y = fmaxf(fmaf(dvn, a[1], b0.y), 0.0f);
    o0.z = fmaxf(fmaf(dvn, a[2], b0.z), 0.0f);
    o0.w = fmaxf(fmaf(dvn, a[3], b0.w), 0.0f);
    o1.x = fmaxf(fmaf(dvn, a[4], b1.x), 0.0f);
    o1.y = fmaxf(fmaf(dvn, a[5], b1.y), 0.0f);
    o1.z = fmaxf(fmaf(dvn, a[6], b1.z), 0.0f);
    o1.w = fmaxf(fmaf(dvn, a[7], b1.w), 0.0f);
    *(float4*)&outp[(size_t)node * F + c8]     = o0;
    *(float4*)&outp[(size_t)node * F + c8 + 4] = o1;
}

template <int F>
static inline int agg2_blocks() {
    int npw = 32 / (F / 8);
    int nodes_per_block = npw * 8;
    return (NN + nodes_per_block - 1) / nodes_per_block;
}

// ---------------- launch ----------------
extern "C" void kernel_launch(void* const* d_in, const int* in_sizes, int n_in,
                              void* d_out, int out_size) {
    const float* x  = (const float*)d_in[0];
    const void*  ei = d_in[1];
    const float* W1 = (const float*)d_in[2];
    const float* b1 = (const float*)d_in[3];
    const float* W2 = (const float*)d_in[4];
    const float* b2 = (const float*)d_in[5];
    const float* W3 = (const float*)d_in[6];
    const float* b3 = (const float*)d_in[7];
    const float* W4 = (const float*)d_in[8];
    const float* b4 = (const float*)d_in[9];
    const float* W5 = (const float*)d_in[10];
    const float* b5 = (const float*)d_in[11];
    float* out = (float*)d_out;

    static float* act = nullptr;
    static cudaStream_t s1 = nullptr;
    static cudaEvent_t evA = nullptr, evB = nullptr;
    if (!act) {
        cudaGetSymbolAddress((void**)&act, g_act);
        cudaStreamCreateWithFlags(&s1, cudaStreamNonBlocking);
        cudaEventCreateWithFlags(&evA, cudaEventDisableTiming);
        cudaEventCreateWithFlags(&evB, cudaEventDisableTiming);
    }

    int nb = (NN + 255) / 256;
    int eb = (NE + 255) / 256;

    // fork: CSR build on s1, layer-1 GEMM (edge-independent) on main stream
    cudaEventRecord(evA, 0);
    cudaStreamWaitEvent(s1, evA, 0);

    k_sniff        <<<1, 32, 0, s1>>>((const unsigned int*)ei);
    k_zero_deg     <<<nb, 256, 0, s1>>>();
    k_prep_edges   <<<eb, 256, 0, s1>>>(ei);
    k_scan1        <<<NBLK, SCAN_B, 0, s1>>>();
    k_scan2        <<<1, 512, 0, s1>>>();
    k_finalize_csr <<<nb, 256, 0, s1>>>();
    k_fill         <<<eb, 256, 0, s1>>>();
    cudaEventRecord(evB, s1);

    gemm128        <<<(NN + 127) / 128, 256>>>(x, W1);

    // join: aggregation needs CSR + dinv
    cudaStreamWaitEvent(0, evB, 0);

    // Layer 1: 128 -> 128
    aggregate1     <<<(NN + 15) / 16, 256>>>(b1, act);

    // Layer 2: 128 -> 64
    gemm_small<128, 64><<<nb, 256>>>(act, W2);
    aggregate2<64> <<<agg2_blocks<64>(), 256>>>(b2, act);

    // Layer 3: 64 -> 32
    gemm_small<64, 32><<<nb, 256>>>(act, W3);
    aggregate2<32> <<<agg2_blocks<32>(), 256>>>(b3, act);

    // Layer 4: 32 -> 16
    gemm_small<32, 16><<<nb, 256>>>(act, W4);
    aggregate2<16> <<<agg2_blocks<16>(), 256>>>(b4, act);

    // Layer 5: 16 -> 8 (output)
    gemm_small<16, 8><<<nb, 256>>>(act, W5);
    aggregate2<8>  <<<agg2_blocks<8>(), 256>>>(b5, out);
}

// round 9
// speedup vs baseline: 1.6554x; 1.4009x over previous
#include <cuda_runtime.h>
#include <cuda_fp16.h>
#include <cstdint>

#define NN 100000
#define NE 1600000
#define SCAN_B 256
#define NBLK ((NN + SCAN_B - 1) / SCAN_B)   // 391

// ---- static device scratch (no allocation allowed) ----
__device__ __align__(16) float  g_dinv[NN];
__device__ __align__(16) int    g_src[NE];
__device__ __align__(16) int    g_dst[NE];
__device__ __align__(16) int    g_col[NE];
__device__ __align__(16) int    g_rowptr[NN + 1];
__device__ __align__(16) int    g_deg[NN];
__device__ __align__(16) int    g_scan[NN];
__device__ __align__(16) int    g_cursor[NN];
__device__ __align__(16) int    g_bsum[NBLK];
__device__ __align__(16) int    g_boff[NBLK];
__device__ __align__(16) __half g_hsh[12800000];  // N x 128 max, fp16 hs
__device__ __align__(16) __half g_ah[12800000];   // act hi (layer-2 input)
__device__ __align__(16) __half g_al[12800000];   // act lo
__device__ __align__(16) float  g_act[12800000];  // fp32 act (layers 3-5)
__device__ __align__(16) __half g_w1h[16384], g_w1l[16384];  // W1^T split [n][k]
__device__ __align__(16) __half g_w2h[8192],  g_w2l[8192];   // W2^T split [n][k]
__device__ int g_is64;

// ---------------- small helpers ----------------
__device__ __forceinline__ uint32_t smem_u32(const void* p) {
    uint32_t a;
    asm("{ .reg .u64 t; cvta.to.shared.u64 t, %1; cvt.u32.u64 %0, t; }"
        : "=r"(a) : "l"(p));
    return a;
}
__device__ __forceinline__ void ldsm4(uint32_t* r, uint32_t addr) {
    asm volatile("ldmatrix.sync.aligned.m8n8.x4.shared.b16 {%0,%1,%2,%3}, [%4];"
        : "=r"(r[0]), "=r"(r[1]), "=r"(r[2]), "=r"(r[3]) : "r"(addr));
}
__device__ __forceinline__ void ldsm2(uint32_t* r, uint32_t addr) {
    asm volatile("ldmatrix.sync.aligned.m8n8.x2.shared.b16 {%0,%1}, [%2];"
        : "=r"(r[0]), "=r"(r[1]) : "r"(addr));
}
__device__ __forceinline__ void mma16816(float* c, const uint32_t* a,
                                         const uint32_t* b) {
    asm volatile("mma.sync.aligned.m16n8k16.row.col.f32.f16.f16.f32 "
        "{%0,%1,%2,%3}, {%4,%5,%6,%7}, {%8,%9}, {%0,%1,%2,%3};"
        : "+f"(c[0]), "+f"(c[1]), "+f"(c[2]), "+f"(c[3])
        : "r"(a[0]), "r"(a[1]), "r"(a[2]), "r"(a[3]), "r"(b[0]), "r"(b[1]));
}

// ---------------- dtype sniff ----------------
__global__ void k_sniff(const unsigned int* __restrict__ w) {
    if (threadIdx.x == 0 && blockIdx.x == 0) {
        int is64 = 1;
        for (int i = 0; i < 128; i++)
            if (w[2 * i + 1] != 0u) { is64 = 0; break; }
        g_is64 = is64;
    }
}

// ---------------- CSR build ----------------
__global__ void k_zero_deg() {
    int i = blockIdx.x * blockDim.x + threadIdx.x;
    if (i < NN) g_deg[i] = 0;
}

__global__ void k_prep_edges(const void* __restrict__ ei) {
    int e = blockIdx.x * blockDim.x + threadIdx.x;
    if (e >= NE) return;
    long long s, d;
    if (g_is64) {
        const long long* p = (const long long*)ei;
        s = p[e]; d = p[NE + e];
    } else {
        const int* p = (const int*)ei;
        s = p[e]; d = p[NE + e];
    }
    if (s >= 0 && s < NN && d >= 0 && d < NN) {
        g_src[e] = (int)s;
        g_dst[e] = (int)d;
        atomicAdd(&g_deg[(int)d], 1);
    } else {
        g_src[e] = -1;   // sentinel
        g_dst[e] = 0;
    }
}

__global__ void k_scan1() {
    __shared__ int sm[SCAN_B];
    int tid = threadIdx.x;
    int i = blockIdx.x * SCAN_B + tid;
    sm[tid] = (i < NN) ? g_deg[i] : 0;
    __syncthreads();
#pragma unroll
    for (int off = 1; off < SCAN_B; off <<= 1) {
        int t = (tid >= off) ? sm[tid - off] : 0;
        __syncthreads();
        if (tid >= off) sm[tid] += t;
        __syncthreads();
    }
    if (i < NN) g_scan[i] = sm[tid];
    if (tid == SCAN_B - 1) g_bsum[blockIdx.x] = sm[SCAN_B - 1];
}

__global__ void k_scan2() {
    __shared__ int sm[512];
    int tid = threadIdx.x;
    sm[tid] = (tid < NBLK) ? g_bsum[tid] : 0;
    __syncthreads();
#pragma unroll
    for (int off = 1; off < 512; off <<= 1) {
        int t = (tid >= off) ? sm[tid - off] : 0;
        __syncthreads();
        if (tid >= off) sm[tid] += t;
        __syncthreads();
    }
    if (tid < NBLK) g_boff[tid] = sm[tid] - g_bsum[tid];   // exclusive
}

__global__ void k_finalize_csr() {
    int i = blockIdx.x * blockDim.x + threadIdx.x;
    if (i >= NN) return;
    int incl = g_scan[i] + g_boff[i / SCAN_B];
    int deg = g_deg[i];
    g_rowptr[i] = incl - deg;
    g_cursor[i] = 0;
    g_dinv[i] = rsqrtf((float)deg + 1.0f);
    if (i == NN - 1) g_rowptr[NN] = incl;
}

__global__ void k_fill() {
    int e = blockIdx.x * blockDim.x + threadIdx.x;
    if (e >= NE) return;
    int s = g_src[e];
    if (s < 0) return;
    int d = g_dst[e];
    int pos = g_rowptr[d] + atomicAdd(&g_cursor[d], 1);
    g_col[pos] = s;
}

// ---------------- W transpose + fp16 split ----------------
__global__ void k_wsplit1(const float* __restrict__ W) {
    int idx = blockIdx.x * blockDim.x + threadIdx.x;
    if (idx >= 128 * 128) return;
    int n = idx >> 7, k = idx & 127;
    float v = W[k * 128 + n];
    __half h = __float2half_rn(v);
    g_w1h[idx] = h;
    g_w1l[idx] = __float2half_rn(v - __half2float(h));
}
__global__ void k_wsplit2(const float* __restrict__ W) {
    int idx = blockIdx.x * blockDim.x + threadIdx.x;
    if (idx >= 64 * 128) return;
    int n = idx >> 7, k = idx & 127;
    float v = W[k * 64 + n];
    __half h = __float2half_rn(v);
    g_w2h[idx] = h;
    g_w2l[idx] = __float2half_rn(v - __half2float(h));
}

// =============== layer-1 GEMM via mma.sync (fp16 split, fp32 acc) ==========
// CTA: 128 rows x 128 cols, K=128, 8 warps (4m x 2n), warp = 32 x 64.
// Writes RAW h (fp16) to g_hsh.
#define STR 136   // padded row stride in halfs
__global__ __launch_bounds__(256) void gemm_mma1(const float* __restrict__ in) {
    extern __shared__ __align__(16) __half sm[];
    __half* ah = sm;
    __half* al = ah + 128 * STR;
    __half* bh = al + 128 * STR;
    __half* bl = bh + 128 * STR;
    int tid = threadIdx.x;
    int rowBase = blockIdx.x * 128;

    // load & split A (x fp32 -> fp16 hi/lo)
#pragma unroll
    for (int i = 0; i < 16; i++) {
        int idx = tid + i * 256;           // 4096 float4 groups
        int r = idx >> 5;
        int c4 = (idx & 31) * 4;
        int gr = rowBase + r;
        float4 v = (gr < NN) ? *(const float4*)&in[(size_t)gr * 128 + c4]
                             : make_float4(0.f, 0.f, 0.f, 0.f);
        __half h0 = __float2half_rn(v.x), h1 = __float2half_rn(v.y);
        __half h2 = __float2half_rn(v.z), h3 = __float2half_rn(v.w);
        __half2 hp0 = __halves2half2(h0, h1), hp1 = __halves2half2(h2, h3);
        __half2 lp0 = __halves2half2(__float2half_rn(v.x - __half2float(h0)),
                                     __float2half_rn(v.y - __half2float(h1)));
        __half2 lp1 = __halves2half2(__float2half_rn(v.z - __half2float(h2)),
                                     __float2half_rn(v.w - __half2float(h3)));
        int off = r * STR + c4;
        *(__half2*)&ah[off] = hp0; *(__half2*)&ah[off + 2] = hp1;
        *(__half2*)&al[off] = lp0; *(__half2*)&al[off + 2] = lp1;
    }
    // load W splits [n][k] -> padded smem
#pragma unroll
    for (int i = 0; i < 8; i++) {
        int idx = tid + i * 256;           // 2048 groups of 8 halfs
        int r = idx >> 4, g = idx & 15;
        int off = r * STR + g * 8;
        *(uint4*)&bh[off] = *(const uint4*)&g_w1h[r * 128 + g * 8];
        *(uint4*)&bl[off] = *(const uint4*)&g_w1l[r * 128 + g * 8];
    }
    __syncthreads();

    int wid = tid >> 5, lane = tid & 31;
    int wm = wid & 3, wn = wid >> 2;
    uint32_t ahb = smem_u32(ah), alb = smem_u32(al);
    uint32_t bhb = smem_u32(bh), blb = smem_u32(bl);
    int arow = wm * 32 + (lane & 15);
    int acol = (lane >> 4) * 8;
    int brow = wn * 64 + (lane & 7);
    int bcol = ((lane >> 3) & 1) * 8;

    float acc[2][8][4];
#pragma unroll
    for (int m = 0; m < 2; m++)
#pragma unroll
        for (int n = 0; n < 8; n++)
#pragma unroll
            for (int q = 0; q < 4; q++) acc[m][n][q] = 0.0f;

#pragma unroll
    for (int kk = 0; kk < 8; kk++) {
        uint32_t afh[2][4], afl[2][4];
#pragma unroll
        for (int m = 0; m < 2; m++) {
            uint32_t ao = (uint32_t)(((arow + m * 16) * STR + kk * 16 + acol) * 2);
            ldsm4(afh[m], ahb + ao);
            ldsm4(afl[m], alb + ao);
        }
        uint32_t bfh[8][2], bfl[8][2];
#pragma unroll
        for (int n = 0; n < 8; n++) {
            uint32_t bo = (uint32_t)(((brow + n * 8) * STR + kk * 16 + bcol) * 2);
            ldsm2(bfh[n], bhb + bo);
            ldsm2(bfl[n], blb + bo);
        }
#pragma unroll
        for (int m = 0; m < 2; m++)
#pragma unroll
            for (int n = 0; n < 8; n++) {
                mma16816(acc[m][n], afh[m], bfh[n]);
                mma16816(acc[m][n], afh[m], bfl[n]);
                mma16816(acc[m][n], afl[m], bfh[n]);
            }
    }

    // epilogue: raw h -> fp16 g_hsh
    int r0 = rowBase + wm * 32 + (lane >> 2);
    int cbase = wn * 64 + 2 * (lane & 3);
#pragma unroll
    for (int m = 0; m < 2; m++) {
        int ra = r0 + m * 16, rb = ra + 8;
#pragma unroll
        for (int n = 0; n < 8; n++) {
            int col = cbase + n * 8;
            if (ra < NN) {
                __half2 p = __floats2half2_rn(acc[m][n][0], acc[m][n][1]);
                *(uint32_t*)&g_hsh[(size_t)ra * 128 + col] = *(uint32_t*)&p;
            }
            if (rb < NN) {
                __half2 p = __floats2half2_rn(acc[m][n][2], acc[m][n][3]);
                *(uint32_t*)&g_hsh[(size_t)rb * 128 + col] = *(uint32_t*)&p;
            }
        }
    }
}

// =============== layer-2 GEMM via mma.sync: [N,128] x [128,64] =============
// Input pre-split (g_ah/g_al). Writes hs = dinv*h (fp16) to g_hsh.
__global__ __launch_bounds__(256) void gemm_mma2() {
    extern __shared__ __align__(16) __half sm[];
    __half* ah = sm;
    __half* al = ah + 128 * STR;
    __half* bh = al + 128 * STR;
    __half* bl = bh + 64 * STR;
    int tid = threadIdx.x;
    int rowBase = blockIdx.x * 128;

    // load pre-split A
#pragma unroll
    for (int i = 0; i < 8; i++) {
        int idx = tid + i * 256;           // 2048 groups of 8 halfs
        int r = idx >> 4, g = idx & 15;
        int gr = rowBase + r;
        int off = r * STR + g * 8;
        if (gr < NN) {
            *(uint4*)&ah[off] = *(const uint4*)&g_ah[(size_t)gr * 128 + g * 8];
            *(uint4*)&al[off] = *(const uint4*)&g_al[(size_t)gr * 128 + g * 8];
        } else {
            uint4 z = make_uint4(0, 0, 0, 0);
            *(uint4*)&ah[off] = z;
            *(uint4*)&al[off] = z;
        }
    }
    // load W2 splits [64][128]
#pragma unroll
    for (int i = 0; i < 4; i++) {
        int idx = tid + i * 256;           // 1024 groups
        int r = idx >> 4, g = idx & 15;
        int off = r * STR + g * 8;
        *(uint4*)&bh[off] = *(const uint4*)&g_w2h[r * 128 + g * 8];
        *(uint4*)&bl[off] = *(const uint4*)&g_w2l[r * 128 + g * 8];
    }
    __syncthreads();

    int wid = tid >> 5, lane = tid & 31;
    int wm = wid & 3, wn = wid >> 2;
    uint32_t ahb = smem_u32(ah), alb = smem_u32(al);
    uint32_t bhb = smem_u32(bh), blb = smem_u32(bl);
    int arow = wm * 32 + (lane & 15);
    int acol = (lane >> 4) * 8;
    int brow = wn * 32 + (lane & 7);
    int bcol = ((lane >> 3) & 1) * 8;

    float acc[2][4][4];
#pragma unroll
    for (int m = 0; m < 2; m++)
#pragma unroll
        for (int n = 0; n < 4; n++)
#pragma unroll
            for (int q = 0; q < 4; q++) acc[m][n][q] = 0.0f;

#pragma unroll
    for (int kk = 0; kk < 8; kk++) {
        uint32_t afh[2][4], afl[2][4];
#pragma unroll
        for (int m = 0; m < 2; m++) {
            uint32_t ao = (uint32_t)(((arow + m * 16) * STR + kk * 16 + acol) * 2);
            ldsm4(afh[m], ahb + ao);
            ldsm4(afl[m], alb + ao);
        }
        uint32_t bfh[4][2], bfl[4][2];
#pragma unroll
        for (int n = 0; n < 4; n++) {
            uint32_t bo = (uint32_t)(((brow + n * 8) * STR + kk * 16 + bcol) * 2);
            ldsm2(bfh[n], bhb + bo);
            ldsm2(bfl[n], blb + bo);
        }
#pragma unroll
        for (int m = 0; m < 2; m++)
#pragma unroll
            for (int n = 0; n < 4; n++) {
                mma16816(acc[m][n], afh[m], bfh[n]);
                mma16816(acc[m][n], afh[m], bfl[n]);
                mma16816(acc[m][n], afl[m], bfh[n]);
            }
    }

    // epilogue: hs = dinv*h -> fp16 g_hsh
    int r0 = rowBase + wm * 32 + (lane >> 2);
    int cbase = wn * 32 + 2 * (lane & 3);
#pragma unroll
    for (int m = 0; m < 2; m++) {
        int ra = r0 + m * 16, rb = ra + 8;
        float da = (ra < NN) ? g_dinv[ra] : 0.0f;
        float db = (rb < NN) ? g_dinv[rb] : 0.0f;
#pragma unroll
        for (int n = 0; n < 4; n++) {
            int col = cbase + n * 8;
            if (ra < NN) {
                __half2 p = __floats2half2_rn(acc[m][n][0] * da, acc[m][n][1] * da);
                *(uint32_t*)&g_hsh[(size_t)ra * 64 + col] = *(uint32_t*)&p;
            }
            if (rb < NN) {
                __half2 p = __floats2half2_rn(acc[m][n][2] * db, acc[m][n][3] * db);
                *(uint32_t*)&g_hsh[(size_t)rb * 64 + col] = *(uint32_t*)&p;
            }
        }
    }
}

// ---------------- GEMM, layers 3-5 (FFMA) ----------------
// Writes hs = dinv[row] * h in fp16.
template <int FIN, int FOUT>
__global__ __launch_bounds__(256) void gemm_small(const float* __restrict__ in,
                                                  const float* __restrict__ W) {
    __shared__ float ws[FIN * FOUT];
    __shared__ float xs[256][9];    // BK=8, padded
    int tid = threadIdx.x;
    for (int i = tid; i < FIN * FOUT; i += 256) ws[i] = W[i];

    int rowBase = blockIdx.x * 256;
    int row = rowBase + tid;
    float acc[FOUT];
#pragma unroll
    for (int j = 0; j < FOUT; j++) acc[j] = 0.0f;

    for (int k0 = 0; k0 < FIN; k0 += 8) {
#pragma unroll
        for (int i = 0; i < 8; i++) {
            int idx = tid + i * 256;
            int r = idx >> 3, c = idx & 7;
            int gr = rowBase + r;
            xs[r][c] = (gr < NN) ? in[gr * FIN + k0 + c] : 0.0f;
        }
        __syncthreads();
#pragma unroll
        for (int k = 0; k < 8; k++) {
            float xv = xs[tid][k];
            const float* wrow = &ws[(k0 + k) * FOUT];
#pragma unroll
            for (int j = 0; j < FOUT; j++)
                acc[j] = fmaf(xv, wrow[j], acc[j]);
        }
        __syncthreads();
    }

    if (row < NN) {
        float dv = g_dinv[row];
#pragma unroll
        for (int j = 0; j < FOUT; j += 8) {
            __half2 ph[4];
#pragma unroll
            for (int q = 0; q < 4; q++)
                ph[q] = __floats2half2_rn(acc[j + 2 * q] * dv,
                                          acc[j + 2 * q + 1] * dv);
            *(uint4*)&g_hsh[(size_t)row * FOUT + j] = *(uint4*)ph;
        }
    }
}

// ---- aggregate layer 1: raw fp16 h, per-edge dinv; writes split act ----
__global__ __launch_bounds__(256) void aggregate1(const float* __restrict__ bias) {
    constexpr int F = 128;
    int warp = (blockIdx.x * 256 + threadIdx.x) >> 5;
    int lane = threadIdx.x & 31;
    int node = warp * 2 + (lane >> 4);
    int c8 = (lane & 15) * 8;
    if (node >= NN) return;

    float dvn = g_dinv[node];
    int beg = g_rowptr[node];
    int end = g_rowptr[node + 1];

    float a[8];
    {
        uint4 raw = *(const uint4*)&g_hsh[(size_t)node * F + c8];
        const __half2* hp = (const __half2*)&raw;
#pragma unroll
        for (int q = 0; q < 4; q++) {
            float2 f = __half22float2(hp[q]);
            a[2 * q]     = dvn * f.x;
            a[2 * q + 1] = dvn * f.y;
        }
    }

    int e = beg;
    for (; e + 1 < end; e += 2) {
        int s0 = g_col[e];
        int s1 = g_col[e + 1];
        float d0 = g_dinv[s0];
        float d1 = g_dinv[s1];
        uint4 r0 = *(const uint4*)&g_hsh[(size_t)s0 * F + c8];
        uint4 r1 = *(const uint4*)&g_hsh[(size_t)s1 * F + c8];
        const __half2* h0 = (const __half2*)&r0;
        const __half2* h1 = (const __half2*)&r1;
#pragma unroll
        for (int q = 0; q < 4; q++) {
            float2 f0 = __half22float2(h0[q]);
            float2 f1 = __half22float2(h1[q]);
            a[2 * q]     = fmaf(d0, f0.x, fmaf(d1, f1.x, a[2 * q]));
            a[2 * q + 1] = fmaf(d0, f0.y, fmaf(d1, f1.y, a[2 * q + 1]));
        }
    }
    if (e < end) {
        int s = g_col[e];
        float ds = g_dinv[s];
        uint4 r = *(const uint4*)&g_hsh[(size_t)s * F + c8];
        const __half2* h = (const __half2*)&r;
#pragma unroll
        for (int q = 0; q < 4; q++) {
            float2 f = __half22float2(h[q]);
            a[2 * q]     = fmaf(ds, f.x, a[2 * q]);
            a[2 * q + 1] = fmaf(ds, f.y, a[2 * q + 1]);
        }
    }

    // relu(dinv*a + b) -> split fp16 (hi/lo)
    __half hh[8], ll[8];
#pragma unroll
    for (int q = 0; q < 8; q++) {
        float b = bias[c8 + q];
        float v = fmaxf(fmaf(dvn, a[q], b), 0.0f);
        __half h = __float2half_rn(v);
        hh[q] = h;
        ll[q] = __float2half_rn(v - __half2float(h));
    }
    *(uint4*)&g_ah[(size_t)node * F + c8] = *(uint4*)hh;
    *(uint4*)&g_al[(size_t)node * F + c8] = *(uint4*)ll;
}

// ---- aggregate layers 2-5: hs pre-scaled; writes fp32 out ----
template <int F>
__global__ __launch_bounds__(256) void aggregate2(const float* __restrict__ bias,
                                                  float* __restrict__ outp) {
    constexpr int L = F / 8;
    constexpr int NPW = 32 / L;
    int warp = (blockIdx.x * 256 + threadIdx.x) >> 5;
    int lane = threadIdx.x & 31;
    int node = warp * NPW + lane / L;
    int c8 = (lane % L) * 8;
    if (node >= NN) return;

    float dvn = g_dinv[node];
    int beg = g_rowptr[node];
    int end = g_rowptr[node + 1];

    float a[8];
    {
        uint4 raw = *(const uint4*)&g_hsh[(size_t)node * F + c8];
        const __half2* hp = (const __half2*)&raw;
#pragma unroll
        for (int q = 0; q < 4; q++) {
            float2 f = __half22float2(hp[q]);
            a[2 * q] = f.x;
            a[2 * q + 1] = f.y;
        }
    }

    int e = beg;
    for (; e + 1 < end; e += 2) {
        int s0 = g_col[e];
        int s1 = g_col[e + 1];
        uint4 r0 = *(const uint4*)&g_hsh[(size_t)s0 * F + c8];
        uint4 r1 = *(const uint4*)&g_hsh[(size_t)s1 * F + c8];
        const __half2* h0 = (const __half2*)&r0;
        const __half2* h1 = (const __half2*)&r1;
#pragma unroll
        for (int q = 0; q < 4; q++) {
            float2 f0 = __half22float2(h0[q]);
            float2 f1 = __half22float2(h1[q]);
            a[2 * q]     += f0.x + f1.x;
            a[2 * q + 1] += f0.y + f1.y;
        }
    }
    if (e < end) {
        int s = g_col[e];
        uint4 r = *(const uint4*)&g_hsh[(size_t)s * F + c8];
        const __half2* h = (const __half2*)&r;
#pragma unroll
        for (int q = 0; q < 4; q++) {
            float2 f = __half22float2(h[q]);
            a[2 * q]     += f.x;
            a[2 * q + 1] += f.y;
        }
    }

    float4 b0 = *(const float4*)&bias[c8];
    float4 b1 = *(const float4*)&bias[c8 + 4];
    float4 o0, o1;
    o0.x = fmaxf(fmaf(dvn, a[0], b0.x), 0.0f);
    o0.y = fmaxf(fmaf(dvn, a[1], b0.y), 0.0f);
    o0.z = fmaxf(fmaf(dvn, a[2], b0.z), 0.0f);
    o0.w = fmaxf(fmaf(dvn, a[3], b0.w), 0.0f);
    o1.x = fmaxf(fmaf(dvn, a[4], b1.x), 0.0f);
    o1.y = fmaxf(fmaf(dvn, a[5], b1.y), 0.0f);
    o1.z = fmaxf(fmaf(dvn, a[6], b1.z), 0.0f);
    o1.w = fmaxf(fmaf(dvn, a[7], b1.w), 0.0f);
    *(float4*)&outp[(size_t)node * F + c8]     = o0;
    *(float4*)&outp[(size_t)node * F + c8 + 4] = o1;
}

template <int F>
static inline int agg2_blocks() {
    int npw = 32 / (F / 8);
    int nodes_per_block = npw * 8;
    return (NN + nodes_per_block - 1) / nodes_per_block;
}

// ---------------- launch ----------------
extern "C" void kernel_launch(void* const* d_in, const int* in_sizes, int n_in,
                              void* d_out, int out_size) {
    const float* x  = (const float*)d_in[0];
    const void*  ei = d_in[1];
    const float* W1 = (const float*)d_in[2];
    const float* b1 = (const float*)d_in[3];
    const float* W2 = (const float*)d_in[4];
    const float* b2 = (const float*)d_in[5];
    const float* W3 = (const float*)d_in[6];
    const float* b3 = (const float*)d_in[7];
    const float* W4 = (const float*)d_in[8];
    const float* b4 = (const float*)d_in[9];
    const float* W5 = (const float*)d_in[10];
    const float* b5 = (const float*)d_in[11];
    float* out = (float*)d_out;

    constexpr int SM1 = 4 * 128 * STR * 2;                 // 139264 B
    constexpr int SM2 = (2 * 128 + 2 * 64) * STR * 2;      // 104448 B

    static float* act = nullptr;
    static cudaStream_t s1 = nullptr;
    static cudaEvent_t evA = nullptr, evB = nullptr;
    if (!act) {
        cudaGetSymbolAddress((void**)&act, g_act);
        cudaStreamCreateWithFlags(&s1, cudaStreamNonBlocking);
        cudaEventCreateWithFlags(&evA, cudaEventDisableTiming);
        cudaEventCreateWithFlags(&evB, cudaEventDisableTiming);
        cudaFuncSetAttribute(gemm_mma1, cudaFuncAttributeMaxDynamicSharedMemorySize, SM1);
        cudaFuncSetAttribute(gemm_mma2, cudaFuncAttributeMaxDynamicSharedMemorySize, SM2);
    }

    int nb = (NN + 255) / 256;
    int eb = (NE + 255) / 256;
    int gt = (NN + 127) / 128;

    // fork: CSR build on s1; W split + layer-1 GEMM on main stream
    cudaEventRecord(evA, 0);
    cudaStreamWaitEvent(s1, evA, 0);

    k_sniff        <<<1, 32, 0, s1>>>((const unsigned int*)ei);
    k_zero_deg     <<<nb, 256, 0, s1>>>();
    k_prep_edges   <<<eb, 256, 0, s1>>>(ei);
    k_scan1        <<<NBLK, SCAN_B, 0, s1>>>();
    k_scan2        <<<1, 512, 0, s1>>>();
    k_finalize_csr <<<nb, 256, 0, s1>>>();
    k_fill         <<<eb, 256, 0, s1>>>();
    cudaEventRecord(evB, s1);

    k_wsplit1      <<<64, 256>>>(W1);
    k_wsplit2      <<<32, 256>>>(W2);
    gemm_mma1      <<<gt, 256, SM1>>>(x);

    // join: aggregation needs CSR + dinv
    cudaStreamWaitEvent(0, evB, 0);

    // Layer 1: 128 -> 128
    aggregate1     <<<(NN + 15) / 16, 256>>>(b1);

    // Layer 2: 128 -> 64 (tensor, pre-split input)
    gemm_mma2      <<<gt, 256, SM2>>>();
    aggregate2<64> <<<agg2_blocks<64>(), 256>>>(b2, act);

    // Layer 3: 64 -> 32
    gemm_small<64, 32><<<nb, 256>>>(act, W3);
    aggregate2<32> <<<agg2_blocks<32>(), 256>>>(b3, act);

    // Layer 4: 32 -> 16
    gemm_small<32, 16><<<nb, 256>>>(act, W4);
    aggregate2<16> <<<agg2_blocks<16>(), 256>>>(b4, act);

    // Layer 5: 16 -> 8 (output)
    gemm_small<16, 8><<<nb, 256>>>(act, W5);
    aggregate2<8>  <<<agg2_blocks<8>(), 256>>>(b5, out);
}

// round 10
// speedup vs baseline: 1.6929x; 1.0227x over previous
#include <cuda_runtime.h>
#include <cuda_fp16.h>
#include <cstdint>

#define NN 100000
#define NE 1600000
#define SCAN_B 256
#define NBLK ((NN + SCAN_B - 1) / SCAN_B)   // 391
#define NSPLIT 50176                         // = 392*128 = 196*256

// ---- static device scratch (no allocation allowed) ----
__device__ __align__(16) float  g_dinv[NN];
__device__ __align__(16) int    g_col[NE];
__device__ __align__(16) int    g_rowptr[NN + 1];
__device__ __align__(16) int    g_deg[NN];
__device__ __align__(16) int    g_scan[NN];
__device__ __align__(16) int    g_cursor[NN];
__device__ __align__(16) int    g_bsum[NBLK];
__device__ __align__(16) int    g_boff[NBLK];
// ping-pong hs buffers (odd layers -> A, even layers -> B)
__device__ __align__(16) __half g_hsA[12800000];   // layers 1(128),3(32),5(8)
__device__ __align__(16) __half g_hsB[6400000];    // layers 2(64),4(16)
// split activations
__device__ __align__(16) __half g_ahA[12800000], g_alA[12800000];  // L1 act (128)
__device__ __align__(16) __half g_ahB[6400000],  g_alB[6400000];   // L2 act (64)
__device__ __align__(16) float  g_act[3200000];    // L3 (32) / L4 (16) act fp32
// W splits (transposed [n][k])
__device__ __align__(16) __half g_w1h[16384], g_w1l[16384];
__device__ __align__(16) __half g_w2h[8192],  g_w2l[8192];
__device__ __align__(16) __half g_w3h[2048],  g_w3l[2048];
__device__ int g_is64;

// ---------------- small helpers ----------------
__device__ __forceinline__ uint32_t smem_u32(const void* p) {
    uint32_t a;
    asm("{ .reg .u64 t; cvta.to.shared.u64 t, %1; cvt.u32.u64 %0, t; }"
        : "=r"(a) : "l"(p));
    return a;
}
__device__ __forceinline__ void ldsm4(uint32_t* r, uint32_t addr) {
    asm volatile("ldmatrix.sync.aligned.m8n8.x4.shared.b16 {%0,%1,%2,%3}, [%4];"
        : "=r"(r[0]), "=r"(r[1]), "=r"(r[2]), "=r"(r[3]) : "r"(addr));
}
__device__ __forceinline__ void ldsm2(uint32_t* r, uint32_t addr) {
    asm volatile("ldmatrix.sync.aligned.m8n8.x2.shared.b16 {%0,%1}, [%2];"
        : "=r"(r[0]), "=r"(r[1]) : "r"(addr));
}
__device__ __forceinline__ void mma16816(float* c, const uint32_t* a,
                                         const uint32_t* b) {
    asm volatile("mma.sync.aligned.m16n8k16.row.col.f32.f16.f16.f32 "
        "{%0,%1,%2,%3}, {%4,%5,%6,%7}, {%8,%9}, {%0,%1,%2,%3};"
        : "+f"(c[0]), "+f"(c[1]), "+f"(c[2]), "+f"(c[3])
        : "r"(a[0]), "r"(a[1]), "r"(a[2]), "r"(a[3]), "r"(b[0]), "r"(b[1]));
}

// ---------------- dtype sniff ----------------
__global__ void k_sniff(const unsigned int* __restrict__ w) {
    if (threadIdx.x == 0 && blockIdx.x == 0) {
        int is64 = 1;
        for (int i = 0; i < 128; i++)
            if (w[2 * i + 1] != 0u) { is64 = 0; break; }
        g_is64 = is64;
    }
}

// ---------------- CSR build (reads edge_index directly) ----------------
__global__ void k_zero_deg() {
    int i = blockIdx.x * blockDim.x + threadIdx.x;
    if (i < NN) g_deg[i] = 0;
}

__global__ void k_deg(const void* __restrict__ ei) {
    int e = blockIdx.x * blockDim.x + threadIdx.x;
    if (e >= NE) return;
    long long s, d;
    if (g_is64) {
        const long long* p = (const long long*)ei;
        s = p[e]; d = p[NE + e];
    } else {
        const int* p = (const int*)ei;
        s = p[e]; d = p[NE + e];
    }
    if (s >= 0 && s < NN && d >= 0 && d < NN)
        atomicAdd(&g_deg[(int)d], 1);
}

__global__ void k_scan1() {
    __shared__ int sm[SCAN_B];
    int tid = threadIdx.x;
    int i = blockIdx.x * SCAN_B + tid;
    sm[tid] = (i < NN) ? g_deg[i] : 0;
    __syncthreads();
#pragma unroll
    for (int off = 1; off < SCAN_B; off <<= 1) {
        int t = (tid >= off) ? sm[tid - off] : 0;
        __syncthreads();
        if (tid >= off) sm[tid] += t;
        __syncthreads();
    }
    if (i < NN) g_scan[i] = sm[tid];
    if (tid == SCAN_B - 1) g_bsum[blockIdx.x] = sm[SCAN_B - 1];
}

__global__ void k_scan2() {
    __shared__ int sm[512];
    int tid = threadIdx.x;
    sm[tid] = (tid < NBLK) ? g_bsum[tid] : 0;
    __syncthreads();
#pragma unroll
    for (int off = 1; off < 512; off <<= 1) {
        int t = (tid >= off) ? sm[tid - off] : 0;
        __syncthreads();
        if (tid >= off) sm[tid] += t;
        __syncthreads();
    }
    if (tid < NBLK) g_boff[tid] = sm[tid] - g_bsum[tid];   // exclusive
}

__global__ void k_finalize_csr() {
    int i = blockIdx.x * blockDim.x + threadIdx.x;
    if (i >= NN) return;
    int incl = g_scan[i] + g_boff[i / SCAN_B];
    int deg = g_deg[i];
    g_rowptr[i] = incl - deg;
    g_cursor[i] = 0;
    g_dinv[i] = rsqrtf((float)deg + 1.0f);
    if (i == NN - 1) g_rowptr[NN] = incl;
}

__global__ void k_fill(const void* __restrict__ ei) {
    int e = blockIdx.x * blockDim.x + threadIdx.x;
    if (e >= NE) return;
    long long s, d;
    if (g_is64) {
        const long long* p = (const long long*)ei;
        s = p[e]; d = p[NE + e];
    } else {
        const int* p = (const int*)ei;
        s = p[e]; d = p[NE + e];
    }
    if (s >= 0 && s < NN && d >= 0 && d < NN) {
        int pos = g_rowptr[(int)d] + atomicAdd(&g_cursor[(int)d], 1);
        g_col[pos] = (int)s;
    }
}

// ---------------- W transpose + fp16 split ----------------
__global__ void k_wsplit1(const float* __restrict__ W) {
    int idx = blockIdx.x * blockDim.x + threadIdx.x;
    if (idx >= 128 * 128) return;
    int n = idx >> 7, k = idx & 127;
    float v = W[k * 128 + n];
    __half h = __float2half_rn(v);
    g_w1h[idx] = h;
    g_w1l[idx] = __float2half_rn(v - __half2float(h));
}
__global__ void k_wsplit2(const float* __restrict__ W) {
    int idx = blockIdx.x * blockDim.x + threadIdx.x;
    if (idx >= 64 * 128) return;
    int n = idx >> 7, k = idx & 127;
    float v = W[k * 64 + n];
    __half h = __float2half_rn(v);
    g_w2h[idx] = h;
    g_w2l[idx] = __float2half_rn(v - __half2float(h));
}
__global__ void k_wsplit3(const float* __restrict__ W) {
    int idx = blockIdx.x * blockDim.x + threadIdx.x;
    if (idx >= 32 * 64) return;
    int n = idx >> 6, k = idx & 63;
    float v = W[k * 32 + n];
    __half h = __float2half_rn(v);
    g_w3h[idx] = h;
    g_w3l[idx] = __float2half_rn(v - __half2float(h));
}

// =============== layer-1 GEMM via mma.sync (fp16 split, fp32 acc) ==========
// CTA: 128 rows x 128 cols, K=128, 8 warps (4m x 2n). Writes RAW h -> g_hsA.
#define STR 136
__global__ __launch_bounds__(256) void gemm_mma1(const float* __restrict__ in) {
    extern __shared__ __align__(16) __half sm[];
    __half* ah = sm;
    __half* al = ah + 128 * STR;
    __half* bh = al + 128 * STR;
    __half* bl = bh + 128 * STR;
    int tid = threadIdx.x;
    int rowBase = blockIdx.x * 128;

#pragma unroll
    for (int i = 0; i < 16; i++) {
        int idx = tid + i * 256;
        int r = idx >> 5;
        int c4 = (idx & 31) * 4;
        int gr = rowBase + r;
        float4 v = (gr < NN) ? *(const float4*)&in[(size_t)gr * 128 + c4]
                             : make_float4(0.f, 0.f, 0.f, 0.f);
        __half h0 = __float2half_rn(v.x), h1 = __float2half_rn(v.y);
        __half h2 = __float2half_rn(v.z), h3 = __float2half_rn(v.w);
        __half2 hp0 = __halves2half2(h0, h1), hp1 = __halves2half2(h2, h3);
        __half2 lp0 = __halves2half2(__float2half_rn(v.x - __half2float(h0)),
                                     __float2half_rn(v.y - __half2float(h1)));
        __half2 lp1 = __halves2half2(__float2half_rn(v.z - __half2float(h2)),
                                     __float2half_rn(v.w - __half2float(h3)));
        int off = r * STR + c4;
        *(__half2*)&ah[off] = hp0; *(__half2*)&ah[off + 2] = hp1;
        *(__half2*)&al[off] = lp0; *(__half2*)&al[off + 2] = lp1;
    }
#pragma unroll
    for (int i = 0; i < 8; i++) {
        int idx = tid + i * 256;
        int r = idx >> 4, g = idx & 15;
        int off = r * STR + g * 8;
        *(uint4*)&bh[off] = *(const uint4*)&g_w1h[r * 128 + g * 8];
        *(uint4*)&bl[off] = *(const uint4*)&g_w1l[r * 128 + g * 8];
    }
    __syncthreads();

    int wid = tid >> 5, lane = tid & 31;
    int wm = wid & 3, wn = wid >> 2;
    uint32_t ahb = smem_u32(ah), alb = smem_u32(al);
    uint32_t bhb = smem_u32(bh), blb = smem_u32(bl);
    int arow = wm * 32 + (lane & 15);
    int acol = (lane >> 4) * 8;
    int brow = wn * 64 + (lane & 7);
    int bcol = ((lane >> 3) & 1) * 8;

    float acc[2][8][4];
#pragma unroll
    for (int m = 0; m < 2; m++)
#pragma unroll
        for (int n = 0; n < 8; n++)
#pragma unroll
            for (int q = 0; q < 4; q++) acc[m][n][q] = 0.0f;

#pragma unroll
    for (int kk = 0; kk < 8; kk++) {
        uint32_t afh[2][4], afl[2][4];
#pragma unroll
        for (int m = 0; m < 2; m++) {
            uint32_t ao = (uint32_t)(((arow + m * 16) * STR + kk * 16 + acol) * 2);
            ldsm4(afh[m], ahb + ao);
            ldsm4(afl[m], alb + ao);
        }
        uint32_t bfh[8][2], bfl[8][2];
#pragma unroll
        for (int n = 0; n < 8; n++) {
            uint32_t bo = (uint32_t)(((brow + n * 8) * STR + kk * 16 + bcol) * 2);
            ldsm2(bfh[n], bhb + bo);
            ldsm2(bfl[n], blb + bo);
        }
#pragma unroll
        for (int m = 0; m < 2; m++)
#pragma unroll
            for (int n = 0; n < 8; n++) {
                mma16816(acc[m][n], afh[m], bfh[n]);
                mma16816(acc[m][n], afh[m], bfl[n]);
                mma16816(acc[m][n], afl[m], bfh[n]);
            }
    }

    int r0 = rowBase + wm * 32 + (lane >> 2);
    int cbase = wn * 64 + 2 * (lane & 3);
#pragma unroll
    for (int m = 0; m < 2; m++) {
        int ra = r0 + m * 16, rb = ra + 8;
#pragma unroll
        for (int n = 0; n < 8; n++) {
            int col = cbase + n * 8;
            if (ra < NN) {
                __half2 p = __floats2half2_rn(acc[m][n][0], acc[m][n][1]);
                *(uint32_t*)&g_hsA[(size_t)ra * 128 + col] = *(uint32_t*)&p;
            }
            if (rb < NN) {
                __half2 p = __floats2half2_rn(acc[m][n][2], acc[m][n][3]);
                *(uint32_t*)&g_hsA[(size_t)rb * 128 + col] = *(uint32_t*)&p;
            }
        }
    }
}

// =============== generic mma GEMM: [128 rows, FIN] x [FIN, FOUT] ===========
// Pre-split fp16 act (Ah/Al), pre-split W (Bh/Bl). Writes hs = dinv*h.
template <int FIN, int FOUT>
__global__ __launch_bounds__(256) void gemm_mmaT(const __half* __restrict__ Ah,
                                                 const __half* __restrict__ Al,
                                                 __half* __restrict__ hsd,
                                                 int rowBase0) {
    constexpr int AST = FIN + 8;
    constexpr int GPR = FIN / 8;
    constexpr int NT = FOUT / 16;
    extern __shared__ __align__(16) __half sm[];
    __half* ah = sm;
    __half* al = ah + 128 * AST;
    __half* bh = al + 128 * AST;
    __half* bl = bh + FOUT * AST;
    int tid = threadIdx.x;
    int rowBase = rowBase0 + blockIdx.x * 128;

    const __half* Bh = (FIN == 128) ? g_w2h : g_w3h;
    const __half* Bl = (FIN == 128) ? g_w2l : g_w3l;

#pragma unroll
    for (int i = 0; i < FIN / 16; i++) {
        int idx = tid + i * 256;
        int r = idx / GPR, g = idx % GPR;
        int gr = rowBase + r;
        int off = r * AST + g * 8;
        if (gr < NN) {
            *(uint4*)&ah[off] = *(const uint4*)&Ah[(size_t)gr * FIN + g * 8];
            *(uint4*)&al[off] = *(const uint4*)&Al[(size_t)gr * FIN + g * 8];
        } else {
            uint4 z = make_uint4(0, 0, 0, 0);
            *(uint4*)&ah[off] = z;
            *(uint4*)&al[off] = z;
        }
    }
#pragma unroll
    for (int i = 0; i < (FOUT * GPR + 255) / 256; i++) {
        int idx = tid + i * 256;
        if (idx < FOUT * GPR) {
            int r = idx / GPR, g = idx % GPR;
            int off = r * AST + g * 8;
            *(uint4*)&bh[off] = *(const uint4*)&Bh[r * FIN + g * 8];
            *(uint4*)&bl[off] = *(const uint4*)&Bl[r * FIN + g * 8];
        }
    }
    __syncthreads();

    int wid = tid >> 5, lane = tid & 31;
    int wm = wid & 3, wn = wid >> 2;
    uint32_t ahb = smem_u32(ah), alb = smem_u32(al);
    uint32_t bhb = smem_u32(bh), blb = smem_u32(bl);
    int arow = wm * 32 + (lane & 15);
    int acol = (lane >> 4) * 8;
    int brow = wn * (FOUT / 2) + (lane & 7);
    int bcol = ((lane >> 3) & 1) * 8;

    float acc[2][NT][4];
#pragma unroll
    for (int m = 0; m < 2; m++)
#pragma unroll
        for (int n = 0; n < NT; n++)
#pragma unroll
            for (int q = 0; q < 4; q++) acc[m][n][q] = 0.0f;

#pragma unroll
    for (int kk = 0; kk < FIN / 16; kk++) {
        uint32_t afh[2][4], afl[2][4];
#pragma unroll
        for (int m = 0; m < 2; m++) {
            uint32_t ao = (uint32_t)(((arow + m * 16) * AST + kk * 16 + acol) * 2);
            ldsm4(afh[m], ahb + ao);
            ldsm4(afl[m], alb + ao);
        }
        uint32_t bfh[NT][2], bfl[NT][2];
#pragma unroll
        for (int n = 0; n < NT; n++) {
            uint32_t bo = (uint32_t)(((brow + n * 8) * AST + kk * 16 + bcol) * 2);
            ldsm2(bfh[n], bhb + bo);
            ldsm2(bfl[n], blb + bo);
        }
#pragma unroll
        for (int m = 0; m < 2; m++)
#pragma unroll
            for (int n = 0; n < NT; n++) {
                mma16816(acc[m][n], afh[m], bfh[n]);
                mma16816(acc[m][n], afh[m], bfl[n]);
                mma16816(acc[m][n], afl[m], bfh[n]);
            }
    }

    int r0 = rowBase + wm * 32 + (lane >> 2);
    int cbase = wn * (FOUT / 2) + 2 * (lane & 3);
#pragma unroll
    for (int m = 0; m < 2; m++) {
        int ra = r0 + m * 16, rb = ra + 8;
        float da = (ra < NN) ? g_dinv[ra] : 0.0f;
        float db = (rb < NN) ? g_dinv[rb] : 0.0f;
#pragma unroll
        for (int n = 0; n < NT; n++) {
            int col = cbase + n * 8;
            if (ra < NN) {
                __half2 p = __floats2half2_rn(acc[m][n][0] * da, acc[m][n][1] * da);
                *(uint32_t*)&hsd[(size_t)ra * FOUT + col] = *(uint32_t*)&p;
            }
            if (rb < NN) {
                __half2 p = __floats2half2_rn(acc[m][n][2] * db, acc[m][n][3] * db);
                *(uint32_t*)&hsd[(size_t)rb * FOUT + col] = *(uint32_t*)&p;
            }
        }
    }
}

// ---------------- GEMM, layers 4-5 (FFMA) ----------------
template <int FIN, int FOUT>
__global__ __launch_bounds__(256) void gemm_small(const float* __restrict__ in,
                                                  const float* __restrict__ W,
                                                  __half* __restrict__ hsd,
                                                  int rowBase0) {
    __shared__ float ws[FIN * FOUT];
    __shared__ float xs[256][9];
    int tid = threadIdx.x;
    for (int i = tid; i < FIN * FOUT; i += 256) ws[i] = W[i];

    int rowBase = rowBase0 + blockIdx.x * 256;
    int row = rowBase + tid;
    float acc[FOUT];
#pragma unroll
    for (int j = 0; j < FOUT; j++) acc[j] = 0.0f;

    for (int k0 = 0; k0 < FIN; k0 += 8) {
#pragma unroll
        for (int i = 0; i < 8; i++) {
            int idx = tid + i * 256;
            int r = idx >> 3, c = idx & 7;
            int gr = rowBase + r;
            xs[r][c] = (gr < NN) ? in[(size_t)gr * FIN + k0 + c] : 0.0f;
        }
        __syncthreads();
#pragma unroll
        for (int k = 0; k < 8; k++) {
            float xv = xs[tid][k];
            const float* wrow = &ws[(k0 + k) * FOUT];
#pragma unroll
            for (int j = 0; j < FOUT; j++)
                acc[j] = fmaf(xv, wrow[j], acc[j]);
        }
        __syncthreads();
    }

    if (row < NN) {
        float dv = g_dinv[row];
#pragma unroll
        for (int j = 0; j < FOUT; j += 8) {
            __half2 ph[4];
#pragma unroll
            for (int q = 0; q < 4; q++)
                ph[q] = __floats2half2_rn(acc[j + 2 * q] * dv,
                                          acc[j + 2 * q + 1] * dv);
            *(uint4*)&hsd[(size_t)row * FOUT + j] = *(uint4*)ph;
        }
    }
}

// ---- aggregate layer 1: raw fp16 h (g_hsA), per-edge dinv; split act ----
__global__ __launch_bounds__(256) void aggregate1(const float* __restrict__ bias,
                                                  int base) {
    constexpr int F = 128;
    int warp = (blockIdx.x * 256 + threadIdx.x) >> 5;
    int lane = threadIdx.x & 31;
    int node = base + warp * 2 + (lane >> 4);
    int c8 = (lane & 15) * 8;
    if (node >= NN) return;

    float dvn = g_dinv[node];
    int beg = g_rowptr[node];
    int end = g_rowptr[node + 1];

    float a[8];
    {
        uint4 raw = *(const uint4*)&g_hsA[(size_t)node * F + c8];
        const __half2* hp = (const __half2*)&raw;
#pragma unroll
        for (int q = 0; q < 4; q++) {
            float2 f = __half22float2(hp[q]);
            a[2 * q]     = dvn * f.x;
            a[2 * q + 1] = dvn * f.y;
        }
    }

    int e = beg;
    for (; e + 1 < end; e += 2) {
        int s0 = g_col[e];
        int s1 = g_col[e + 1];
        float d0 = g_dinv[s0];
        float d1 = g_dinv[s1];
        uint4 r0 = *(const uint4*)&g_hsA[(size_t)s0 * F + c8];
        uint4 r1 = *(const uint4*)&g_hsA[(size_t)s1 * F + c8];
        const __half2* h0 = (const __half2*)&r0;
        const __half2* h1 = (const __half2*)&r1;
#pragma unroll
        for (int q = 0; q < 4; q++) {
            float2 f0 = __half22float2(h0[q]);
            float2 f1 = __half22float2(h1[q]);
            a[2 * q]     = fmaf(d0, f0.x, fmaf(d1, f1.x, a[2 * q]));
            a[2 * q + 1] = fmaf(d0, f0.y, fmaf(d1, f1.y, a[2 * q + 1]));
        }
    }
    if (e < end) {
        int s = g_col[e];
        float ds = g_dinv[s];
        uint4 r = *(const uint4*)&g_hsA[(size_t)s * F + c8];
        const __half2* h = (const __half2*)&r;
#pragma unroll
        for (int q = 0; q < 4; q++) {
            float2 f = __half22float2(h[q]);
            a[2 * q]     = fmaf(ds, f.x, a[2 * q]);
            a[2 * q + 1] = fmaf(ds, f.y, a[2 * q + 1]);
        }
    }

    __half hh[8], ll[8];
#pragma unroll
    for (int q = 0; q < 8; q++) {
        float b = bias[c8 + q];
        float v = fmaxf(fmaf(dvn, a[q], b), 0.0f);
        __half h = __float2half_rn(v);
        hh[q] = h;
        ll[q] = __float2half_rn(v - __half2float(h));
    }
    *(uint4*)&g_ahA[(size_t)node * F + c8] = *(uint4*)hh;
    *(uint4*)&g_alA[(size_t)node * F + c8] = *(uint4*)ll;
}

// ---- aggregate layer 2 (F=64, hs in g_hsB pre-scaled): split act out ----
__global__ __launch_bounds__(256) void agg_split64(const float* __restrict__ bias,
                                                   int base) {
    constexpr int F = 64;
    int warp = (blockIdx.x * 256 + threadIdx.x) >> 5;
    int lane = threadIdx.x & 31;
    int node = base + warp * 4 + lane / 8;
    int c8 = (lane % 8) * 8;
    if (node >= NN) return;

    float dvn = g_dinv[node];
    int beg = g_rowptr[node];
    int end = g_rowptr[node + 1];

    float a[8];
    {
        uint4 raw = *(const uint4*)&g_hsB[(size_t)node * F + c8];
        const __half2* hp = (const __half2*)&raw;
#pragma unroll
        for (int q = 0; q < 4; q++) {
            float2 f = __half22float2(hp[q]);
            a[2 * q] = f.x;
            a[2 * q + 1] = f.y;
        }
    }
    int e = beg;
    for (; e + 1 < end; e += 2) {
        int s0 = g_col[e];
        int s1 = g_col[e + 1];
        uint4 r0 = *(const uint4*)&g_hsB[(size_t)s0 * F + c8];
        uint4 r1 = *(const uint4*)&g_hsB[(size_t)s1 * F + c8];
        const __half2* h0 = (const __half2*)&r0;
        const __half2* h1 = (const __half2*)&r1;
#pragma unroll
        for (int q = 0; q < 4; q++) {
            float2 f0 = __half22float2(h0[q]);
            float2 f1 = __half22float2(h1[q]);
            a[2 * q]     += f0.x + f1.x;
            a[2 * q + 1] += f0.y + f1.y;
        }
    }
    if (e < end) {
        int s = g_col[e];
        uint4 r = *(const uint4*)&g_hsB[(size_t)s * F + c8];
        const __half2* h = (const __half2*)&r;
#pragma unroll
        for (int q = 0; q < 4; q++) {
            float2 f = __half22float2(h[q]);
            a[2 * q]     += f.x;
            a[2 * q + 1] += f.y;
        }
    }

    __half hh[8], ll[8];
#pragma unroll
    for (int q = 0; q < 8; q++) {
        float b = bias[c8 + q];
        float v = fmaxf(fmaf(dvn, a[q], b), 0.0f);
        __half h = __float2half_rn(v);
        hh[q] = h;
        ll[q] = __float2half_rn(v - __half2float(h));
    }
    *(uint4*)&g_ahB[(size_t)node * F + c8] = *(uint4*)hh;
    *(uint4*)&g_alB[(size_t)node * F + c8] = *(uint4*)ll;
}

// ---- aggregate layers 3-5: hs pre-scaled; fp32 out ----
template <int F>
__global__ __launch_bounds__(256) void aggregate2(const float* __restrict__ bias,
                                                  float* __restrict__ outp,
                                                  const __half* __restrict__ hs,
                                                  int base) {
    constexpr int L = F / 8;
    constexpr int NPW = 32 / L;
    int warp = (blockIdx.x * 256 + threadIdx.x) >> 5;
    int lane = threadIdx.x & 31;
    int node = base + warp * NPW + lane / L;
    int c8 = (lane % L) * 8;
    if (node >= NN) return;

    float dvn = g_dinv[node];
    int beg = g_rowptr[node];
    int end = g_rowptr[node + 1];

    float a[8];
    {
        uint4 raw = *(const uint4*)&hs[(size_t)node * F + c8];
        const __half2* hp = (const __half2*)&raw;
#pragma unroll
        for (int q = 0; q < 4; q++) {
            float2 f = __half22float2(hp[q]);
            a[2 * q] = f.x;
            a[2 * q + 1] = f.y;
        }
    }
    int e = beg;
    for (; e + 1 < end; e += 2) {
        int s0 = g_col[e];
        int s1 = g_col[e + 1];
        uint4 r0 = *(const uint4*)&hs[(size_t)s0 * F + c8];
        uint4 r1 = *(const uint4*)&hs[(size_t)s1 * F + c8];
        const __half2* h0 = (const __half2*)&r0;
        const __half2* h1 = (const __half2*)&r1;
#pragma unroll
        for (int q = 0; q < 4; q++) {
            float2 f0 = __half22float2(h0[q]);
            float2 f1 = __half22float2(h1[q]);
            a[2 * q]     += f0.x + f1.x;
            a[2 * q + 1] += f0.y + f1.y;
        }
    }
    if (e < end) {
        int s = g_col[e];
        uint4 r = *(const uint4*)&hs[(size_t)s * F + c8];
        const __half2* h = (const __half2*)&r;
#pragma unroll
        for (int q = 0; q < 4; q++) {
            float2 f = __half22float2(h[q]);
            a[2 * q]     += f.x;
            a[2 * q + 1] += f.y;
        }
    }

    float4 b0 = *(const float4*)&bias[c8];
    float4 b1 = *(const float4*)&bias[c8 + 4];
    float4 o0, o1;
    o0.x = fmaxf(fmaf(dvn, a[0], b0.x), 0.0f);
    o0.y = fmaxf(fmaf(dvn, a[1], b0.y), 0.0f);
    o0.z = fmaxf(fmaf(dvn, a[2], b0.z), 0.0f);
    o0.w = fmaxf(fmaf(dvn, a[3], b0.w), 0.0f);
    o1.x = fmaxf(fmaf(dvn, a[4], b1.x), 0.0f);
    o1.y = fmaxf(fmaf(dvn, a[5], b1.y), 0.0f);
    o1.z = fmaxf(fmaf(dvn, a[6], b1.z), 0.0f);
    o1.w = fmaxf(fmaf(dvn, a[7], b1.w), 0.0f);
    *(float4*)&outp[(size_t)node * F + c8]     = o0;
    *(float4*)&outp[(size_t)node * F + c8 + 4] = o1;
}

static inline int blocks_for(int count, int npb) {
    return (count + npb - 1) / npb;
}

// ---------------- launch ----------------
extern "C" void kernel_launch(void* const* d_in, const int* in_sizes, int n_in,
                              void* d_out, int out_size) {
    const float* x  = (const float*)d_in[0];
    const void*  ei = d_in[1];
    const float* W1 = (const float*)d_in[2];
    const float* b1 = (const float*)d_in[3];
    const float* b2 = (const float*)d_in[5];
    const float* W2 = (const float*)d_in[4];
    const float* W3 = (const float*)d_in[6];
    const float* b3 = (const float*)d_in[7];
    const float* W4 = (const float*)d_in[8];
    const float* b4 = (const float*)d_in[9];
    const float* W5 = (const float*)d_in[10];
    const float* b5 = (const float*)d_in[11];
    float* out = (float*)d_out;

    constexpr int SM1 = 4 * 128 * STR * 2;                    // 139264
    constexpr int SM2 = (2 * 128 + 2 * 64) * 136 * 2;         // 104448
    constexpr int SM3 = (2 * 128 + 2 * 32) * 72 * 2;          //  46080

    static float* act = nullptr;
    static __half *ahA, *alA, *ahB, *alB, *hsA, *hsB;
    static cudaStream_t s1 = nullptr;
    static cudaEvent_t evF, evPrep, evG1, evA1h1, evG2, evA2h1, evG3, evA3h1;
    if (!act) {
        cudaGetSymbolAddress((void**)&act, g_act);
        cudaGetSymbolAddress((void**)&ahA, g_ahA);
        cudaGetSymbolAddress((void**)&alA, g_alA);
        cudaGetSymbolAddress((void**)&ahB, g_ahB);
        cudaGetSymbolAddress((void**)&alB, g_alB);
        cudaGetSymbolAddress((void**)&hsA, g_hsA);
        cudaGetSymbolAddress((void**)&hsB, g_hsB);
        cudaStreamCreateWithFlags(&s1, cudaStreamNonBlocking);
        cudaEventCreateWithFlags(&evF,    cudaEventDisableTiming);
        cudaEventCreateWithFlags(&evPrep, cudaEventDisableTiming);
        cudaEventCreateWithFlags(&evG1,   cudaEventDisableTiming);
        cudaEventCreateWithFlags(&evA1h1, cudaEventDisableTiming);
        cudaEventCreateWithFlags(&evG2,   cudaEventDisableTiming);
        cudaEventCreateWithFlags(&evA2h1, cudaEventDisableTiming);
        cudaEventCreateWithFlags(&evG3,   cudaEventDisableTiming);
        cudaEventCreateWithFlags(&evA3h1, cudaEventDisableTiming);
        cudaFuncSetAttribute(gemm_mma1, cudaFuncAttributeMaxDynamicSharedMemorySize, SM1);
        cudaFuncSetAttribute(gemm_mmaT<128, 64>, cudaFuncAttributeMaxDynamicSharedMemorySize, SM2);
        cudaFuncSetAttribute(gemm_mmaT<64, 32>, cudaFuncAttributeMaxDynamicSharedMemorySize, SM3);
    }

    const int H0 = NSPLIT, H1 = NN - NSPLIT;
    int nb = (NN + 255) / 256;
    int eb = (NE + 255) / 256;

    // fork: CSR build on s1; W split + layer-1 GEMM on s0
    cudaEventRecord(evF, 0);
    cudaStreamWaitEvent(s1, evF, 0);

    k_sniff        <<<1, 32, 0, s1>>>((const unsigned int*)ei);
    k_zero_deg     <<<nb, 256, 0, s1>>>();
    k_deg          <<<eb, 256, 0, s1>>>(ei);
    k_scan1        <<<NBLK, SCAN_B, 0, s1>>>();
    k_scan2        <<<1, 512, 0, s1>>>();
    k_finalize_csr <<<nb, 256, 0, s1>>>();
    k_fill         <<<eb, 256, 0, s1>>>(ei);
    cudaEventRecord(evPrep, s1);

    k_wsplit1 <<<64, 256>>>(W1);
    k_wsplit2 <<<32, 256>>>(W2);
    k_wsplit3 <<<8, 256>>>(W3);
    gemm_mma1 <<<(NN + 127) / 128, 256, SM1>>>(x);
    cudaEventRecord(evG1, 0);

    // ---- layer 1 aggregate, split halves ----
    cudaStreamWaitEvent(s1, evG1, 0);
    aggregate1 <<<blocks_for(H1, 16), 256, 0, s1>>>(b1, NSPLIT);
    cudaEventRecord(evA1h1, s1);

    cudaStreamWaitEvent(0, evPrep, 0);
    aggregate1 <<<blocks_for(H0, 16), 256>>>(b1, 0);

    // ---- layer 2 gemm (mma), pipelined with A1 half1 ----
    gemm_mmaT<128, 64> <<<H0 / 128, 256, SM2>>>(ahA, alA, hsB, 0);
    cudaStreamWaitEvent(0, evA1h1, 0);
    gemm_mmaT<128, 64> <<<blocks_for(H1, 128), 256, SM2>>>(ahA, alA, hsB, NSPLIT);
    cudaEventRecord(evG2, 0);

    // ---- layer 2 aggregate (split fp16 out), halves ----
    cudaStreamWaitEvent(s1, evG2, 0);
    agg_split64 <<<blocks_for(H1, 32), 256, 0, s1>>>(b2, NSPLIT);
    cudaEventRecord(evA2h1, s1);
    agg_split64 <<<blocks_for(H0, 32), 256>>>(b2, 0);

    // ---- layer 3 gemm (mma), pipelined ----
    gemm_mmaT<64, 32> <<<H0 / 128, 256, SM3>>>(ahB, alB, hsA, 0);
    cudaStreamWaitEvent(0, evA2h1, 0);
    gemm_mmaT<64, 32> <<<blocks_for(H1, 128), 256, SM3>>>(ahB, alB, hsA, NSPLIT);
    cudaEventRecord(evG3, 0);

    // ---- layer 3 aggregate (fp32 act out), halves ----
    cudaStreamWaitEvent(s1, evG3, 0);
    aggregate2<32> <<<blocks_for(H1, 64), 256, 0, s1>>>(b3, act, hsA, NSPLIT);
    cudaEventRecord(evA3h1, s1);
    aggregate2<32> <<<blocks_for(H0, 64), 256>>>(b3, act, hsA, 0);

    // ---- layer 4 gemm (FFMA), pipelined ----
    gemm_small<32, 16> <<<H0 / 256, 256>>>(act, W4, hsB, 0);
    cudaStreamWaitEvent(0, evA3h1, 0);
    gemm_small<32, 16> <<<blocks_for(H1, 256), 256>>>(act, W4, hsB, NSPLIT);

    // ---- tail, sequential on s0 ----
    aggregate2<16> <<<blocks_for(NN, 128), 256>>>(b4, act, hsB, 0);
    gemm_small<16, 8> <<<nb, 256>>>(act, W5, hsA, 0);
    aggregate2<8> <<<blocks_for(NN, 256), 256>>>(b5, out, hsA, 0);
}

// round 11
// speedup vs baseline: 1.7926x; 1.0589x over previous
#include <cuda_runtime.h>
#include <cuda_fp16.h>
#include <cstdint>

#define NN 100000
#define NE 1600000
#define SCAN_B 256
#define NBLK ((NN + SCAN_B - 1) / SCAN_B)   // 391
#define NSPLIT 50176                         // = 392*128 = 196*256

// ---- static device scratch (no allocation allowed) ----
__device__ __align__(16) float  g_dinv[NN];
__device__ __align__(16) int    g_col[NE];
__device__ __align__(16) int    g_rowptr[NN + 1];
__device__ __align__(16) int    g_deg[NN];
__device__ __align__(16) int    g_scan[NN];
__device__ __align__(16) int    g_cursor[NN];
__device__ __align__(16) int    g_bsum[NBLK];
__device__ __align__(16) int    g_boff[NBLK];
// ping-pong hs buffers (odd layers -> A, even layers -> B)
__device__ __align__(16) __half g_hsA[12800000];   // layers 1(128),3(32),5(8)
__device__ __align__(16) __half g_hsB[6400000];    // layers 2(64),4(16)
// fp16 activations (single precision level; W carries the split)
__device__ __align__(16) __half g_ahA[12800000];   // L1 act (128)
__device__ __align__(16) __half g_ahB[6400000];    // L2 act (64)
__device__ __align__(16) float  g_act[3200000];    // L3 (32) / L4 (16) act fp32
// W splits (transposed [n][k])
__device__ __align__(16) __half g_w1h[16384], g_w1l[16384];
__device__ __align__(16) __half g_w2h[8192],  g_w2l[8192];
__device__ __align__(16) __half g_w3h[2048],  g_w3l[2048];
__device__ int g_is64;

// ---------------- small helpers ----------------
__device__ __forceinline__ uint32_t smem_u32(const void* p) {
    uint32_t a;
    asm("{ .reg .u64 t; cvta.to.shared.u64 t, %1; cvt.u32.u64 %0, t; }"
        : "=r"(a) : "l"(p));
    return a;
}
__device__ __forceinline__ void ldsm4(uint32_t* r, uint32_t addr) {
    asm volatile("ldmatrix.sync.aligned.m8n8.x4.shared.b16 {%0,%1,%2,%3}, [%4];"
        : "=r"(r[0]), "=r"(r[1]), "=r"(r[2]), "=r"(r[3]) : "r"(addr));
}
__device__ __forceinline__ void ldsm2(uint32_t* r, uint32_t addr) {
    asm volatile("ldmatrix.sync.aligned.m8n8.x2.shared.b16 {%0,%1}, [%2];"
        : "=r"(r[0]), "=r"(r[1]) : "r"(addr));
}
__device__ __forceinline__ void mma16816(float* c, const uint32_t* a,
                                         const uint32_t* b) {
    asm volatile("mma.sync.aligned.m16n8k16.row.col.f32.f16.f16.f32 "
        "{%0,%1,%2,%3}, {%4,%5,%6,%7}, {%8,%9}, {%0,%1,%2,%3};"
        : "+f"(c[0]), "+f"(c[1]), "+f"(c[2]), "+f"(c[3])
        : "r"(a[0]), "r"(a[1]), "r"(a[2]), "r"(a[3]), "r"(b[0]), "r"(b[1]));
}

// ---------------- sniff + zero deg (merged) ----------------
__global__ void k_sniff_zero(const unsigned int* __restrict__ w) {
    int i = blockIdx.x * blockDim.x + threadIdx.x;
    if (i < NN) g_deg[i] = 0;
    if (i == 0) {
        int is64 = 1;
        for (int q = 0; q < 128; q++)
            if (w[2 * q + 1] != 0u) { is64 = 0; break; }
        g_is64 = is64;
    }
}

__global__ void k_deg(const void* __restrict__ ei) {
    int e = blockIdx.x * blockDim.x + threadIdx.x;
    if (e >= NE) return;
    long long s, d;
    if (g_is64) {
        const long long* p = (const long long*)ei;
        s = p[e]; d = p[NE + e];
    } else {
        const int* p = (const int*)ei;
        s = p[e]; d = p[NE + e];
    }
    if (s >= 0 && s < NN && d >= 0 && d < NN)
        atomicAdd(&g_deg[(int)d], 1);
}

__global__ void k_scan1() {
    __shared__ int sm[SCAN_B];
    int tid = threadIdx.x;
    int i = blockIdx.x * SCAN_B + tid;
    sm[tid] = (i < NN) ? g_deg[i] : 0;
    __syncthreads();
#pragma unroll
    for (int off = 1; off < SCAN_B; off <<= 1) {
        int t = (tid >= off) ? sm[tid - off] : 0;
        __syncthreads();
        if (tid >= off) sm[tid] += t;
        __syncthreads();
    }
    if (i < NN) g_scan[i] = sm[tid];
    if (tid == SCAN_B - 1) g_bsum[blockIdx.x] = sm[SCAN_B - 1];
}

__global__ void k_scan2() {
    __shared__ int sm[512];
    int tid = threadIdx.x;
    sm[tid] = (tid < NBLK) ? g_bsum[tid] : 0;
    __syncthreads();
#pragma unroll
    for (int off = 1; off < 512; off <<= 1) {
        int t = (tid >= off) ? sm[tid - off] : 0;
        __syncthreads();
        if (tid >= off) sm[tid] += t;
        __syncthreads();
    }
    if (tid < NBLK) g_boff[tid] = sm[tid] - g_bsum[tid];   // exclusive
}

__global__ void k_finalize_csr() {
    int i = blockIdx.x * blockDim.x + threadIdx.x;
    if (i >= NN) return;
    int incl = g_scan[i] + g_boff[i / SCAN_B];
    int deg = g_deg[i];
    g_rowptr[i] = incl - deg;
    g_cursor[i] = 0;
    g_dinv[i] = rsqrtf((float)deg + 1.0f);
    if (i == NN - 1) g_rowptr[NN] = incl;
}

__global__ void k_fill(const void* __restrict__ ei) {
    int e = blockIdx.x * blockDim.x + threadIdx.x;
    if (e >= NE) return;
    long long s, d;
    if (g_is64) {
        const long long* p = (const long long*)ei;
        s = p[e]; d = p[NE + e];
    } else {
        const int* p = (const int*)ei;
        s = p[e]; d = p[NE + e];
    }
    if (s >= 0 && s < NN && d >= 0 && d < NN) {
        int pos = g_rowptr[(int)d] + atomicAdd(&g_cursor[(int)d], 1);
        g_col[pos] = (int)s;
    }
}

// ---------------- W transpose + fp16 split ----------------
__global__ void k_wsplit1(const float* __restrict__ W) {
    int idx = blockIdx.x * blockDim.x + threadIdx.x;
    if (idx >= 128 * 128) return;
    int n = idx >> 7, k = idx & 127;
    float v = W[k * 128 + n];
    __half h = __float2half_rn(v);
    g_w1h[idx] = h;
    g_w1l[idx] = __float2half_rn(v - __half2float(h));
}
__global__ void k_wsplit2(const float* __restrict__ W) {
    int idx = blockIdx.x * blockDim.x + threadIdx.x;
    if (idx >= 64 * 128) return;
    int n = idx >> 7, k = idx & 127;
    float v = W[k * 64 + n];
    __half h = __float2half_rn(v);
    g_w2h[idx] = h;
    g_w2l[idx] = __float2half_rn(v - __half2float(h));
}
__global__ void k_wsplit3(const float* __restrict__ W) {
    int idx = blockIdx.x * blockDim.x + threadIdx.x;
    if (idx >= 32 * 64) return;
    int n = idx >> 6, k = idx & 63;
    float v = W[k * 32 + n];
    __half h = __float2half_rn(v);
    g_w3h[idx] = h;
    g_w3l[idx] = __float2half_rn(v - __half2float(h));
}

// =============== layer-1 GEMM: A fp16, W split, fp32 acc ===================
// CTA: 128 rows x 128 cols, K=128, 8 warps (4m x 2n). Writes RAW h -> g_hsA.
#define STR 136
__global__ __launch_bounds__(256) void gemm_mma1(const float* __restrict__ in) {
    extern __shared__ __align__(16) __half sm[];
    __half* ah = sm;
    __half* bh = ah + 128 * STR;
    __half* bl = bh + 128 * STR;
    int tid = threadIdx.x;
    int rowBase = blockIdx.x * 128;

#pragma unroll
    for (int i = 0; i < 16; i++) {
        int idx = tid + i * 256;
        int r = idx >> 5;
        int c4 = (idx & 31) * 4;
        int gr = rowBase + r;
        float4 v = (gr < NN) ? *(const float4*)&in[(size_t)gr * 128 + c4]
                             : make_float4(0.f, 0.f, 0.f, 0.f);
        __half2 hp0 = __floats2half2_rn(v.x, v.y);
        __half2 hp1 = __floats2half2_rn(v.z, v.w);
        int off = r * STR + c4;
        *(__half2*)&ah[off] = hp0;
        *(__half2*)&ah[off + 2] = hp1;
    }
#pragma unroll
    for (int i = 0; i < 8; i++) {
        int idx = tid + i * 256;
        int r = idx >> 4, g = idx & 15;
        int off = r * STR + g * 8;
        *(uint4*)&bh[off] = *(const uint4*)&g_w1h[r * 128 + g * 8];
        *(uint4*)&bl[off] = *(const uint4*)&g_w1l[r * 128 + g * 8];
    }
    __syncthreads();

    int wid = tid >> 5, lane = tid & 31;
    int wm = wid & 3, wn = wid >> 2;
    uint32_t ahb = smem_u32(ah);
    uint32_t bhb = smem_u32(bh), blb = smem_u32(bl);
    int arow = wm * 32 + (lane & 15);
    int acol = (lane >> 4) * 8;
    int brow = wn * 64 + (lane & 7);
    int bcol = ((lane >> 3) & 1) * 8;

    float acc[2][8][4];
#pragma unroll
    for (int m = 0; m < 2; m++)
#pragma unroll
        for (int n = 0; n < 8; n++)
#pragma unroll
            for (int q = 0; q < 4; q++) acc[m][n][q] = 0.0f;

#pragma unroll
    for (int kk = 0; kk < 8; kk++) {
        uint32_t afh[2][4];
#pragma unroll
        for (int m = 0; m < 2; m++) {
            uint32_t ao = (uint32_t)(((arow + m * 16) * STR + kk * 16 + acol) * 2);
            ldsm4(afh[m], ahb + ao);
        }
        uint32_t bfh[8][2], bfl[8][2];
#pragma unroll
        for (int n = 0; n < 8; n++) {
            uint32_t bo = (uint32_t)(((brow + n * 8) * STR + kk * 16 + bcol) * 2);
            ldsm2(bfh[n], bhb + bo);
            ldsm2(bfl[n], blb + bo);
        }
#pragma unroll
        for (int m = 0; m < 2; m++)
#pragma unroll
            for (int n = 0; n < 8; n++) {
                mma16816(acc[m][n], afh[m], bfh[n]);
                mma16816(acc[m][n], afh[m], bfl[n]);
            }
    }

    int r0 = rowBase + wm * 32 + (lane >> 2);
    int cbase = wn * 64 + 2 * (lane & 3);
#pragma unroll
    for (int m = 0; m < 2; m++) {
        int ra = r0 + m * 16, rb = ra + 8;
#pragma unroll
        for (int n = 0; n < 8; n++) {
            int col = cbase + n * 8;
            if (ra < NN) {
                __half2 p = __floats2half2_rn(acc[m][n][0], acc[m][n][1]);
                *(uint32_t*)&g_hsA[(size_t)ra * 128 + col] = *(uint32_t*)&p;
            }
            if (rb < NN) {
                __half2 p = __floats2half2_rn(acc[m][n][2], acc[m][n][3]);
                *(uint32_t*)&g_hsA[(size_t)rb * 128 + col] = *(uint32_t*)&p;
            }
        }
    }
}

// =============== generic mma GEMM: [128 rows, FIN] x [FIN, FOUT] ===========
// A single fp16, W split. Writes hs = dinv*h.
template <int FIN, int FOUT>
__global__ __launch_bounds__(256) void gemm_mmaT(const __half* __restrict__ Ah,
                                                 __half* __restrict__ hsd,
                                                 int rowBase0) {
    constexpr int AST = FIN + 8;
    constexpr int GPR = FIN / 8;
    constexpr int NT = FOUT / 16;
    extern __shared__ __align__(16) __half sm[];
    __half* ah = sm;
    __half* bh = ah + 128 * AST;
    __half* bl = bh + FOUT * AST;
    int tid = threadIdx.x;
    int rowBase = rowBase0 + blockIdx.x * 128;

    const __half* Bh = (FIN == 128) ? g_w2h : g_w3h;
    const __half* Bl = (FIN == 128) ? g_w2l : g_w3l;

#pragma unroll
    for (int i = 0; i < FIN / 16; i++) {
        int idx = tid + i * 256;
        int r = idx / GPR, g = idx % GPR;
        int gr = rowBase + r;
        int off = r * AST + g * 8;
        if (gr < NN) {
            *(uint4*)&ah[off] = *(const uint4*)&Ah[(size_t)gr * FIN + g * 8];
        } else {
            *(uint4*)&ah[off] = make_uint4(0, 0, 0, 0);
        }
    }
#pragma unroll
    for (int i = 0; i < (FOUT * GPR + 255) / 256; i++) {
        int idx = tid + i * 256;
        if (idx < FOUT * GPR) {
            int r = idx / GPR, g = idx % GPR;
            int off = r * AST + g * 8;
            *(uint4*)&bh[off] = *(const uint4*)&Bh[r * FIN + g * 8];
            *(uint4*)&bl[off] = *(const uint4*)&Bl[r * FIN + g * 8];
        }
    }
    __syncthreads();

    int wid = tid >> 5, lane = tid & 31;
    int wm = wid & 3, wn = wid >> 2;
    uint32_t ahb = smem_u32(ah);
    uint32_t bhb = smem_u32(bh), blb = smem_u32(bl);
    int arow = wm * 32 + (lane & 15);
    int acol = (lane >> 4) * 8;
    int brow = wn * (FOUT / 2) + (lane & 7);
    int bcol = ((lane >> 3) & 1) * 8;

    float acc[2][NT][4];
#pragma unroll
    for (int m = 0; m < 2; m++)
#pragma unroll
        for (int n = 0; n < NT; n++)
#pragma unroll
            for (int q = 0; q < 4; q++) acc[m][n][q] = 0.0f;

#pragma unroll
    for (int kk = 0; kk < FIN / 16; kk++) {
        uint32_t afh[2][4];
#pragma unroll
        for (int m = 0; m < 2; m++) {
            uint32_t ao = (uint32_t)(((arow + m * 16) * AST + kk * 16 + acol) * 2);
            ldsm4(afh[m], ahb + ao);
        }
        uint32_t bfh[NT][2], bfl[NT][2];
#pragma unroll
        for (int n = 0; n < NT; n++) {
            uint32_t bo = (uint32_t)(((brow + n * 8) * AST + kk * 16 + bcol) * 2);
            ldsm2(bfh[n], bhb + bo);
            ldsm2(bfl[n], blb + bo);
        }
#pragma unroll
        for (int m = 0; m < 2; m++)
#pragma unroll
            for (int n = 0; n < NT; n++) {
                mma16816(acc[m][n], afh[m], bfh[n]);
                mma16816(acc[m][n], afh[m], bfl[n]);
            }
    }

    int r0 = rowBase + wm * 32 + (lane >> 2);
    int cbase = wn * (FOUT / 2) + 2 * (lane & 3);
#pragma unroll
    for (int m = 0; m < 2; m++) {
        int ra = r0 + m * 16, rb = ra + 8;
        float da = (ra < NN) ? g_dinv[ra] : 0.0f;
        float db = (rb < NN) ? g_dinv[rb] : 0.0f;
#pragma unroll
        for (int n = 0; n < NT; n++) {
            int col = cbase + n * 8;
            if (ra < NN) {
                __half2 p = __floats2half2_rn(acc[m][n][0] * da, acc[m][n][1] * da);
                *(uint32_t*)&hsd[(size_t)ra * FOUT + col] = *(uint32_t*)&p;
            }
            if (rb < NN) {
                __half2 p = __floats2half2_rn(acc[m][n][2] * db, acc[m][n][3] * db);
                *(uint32_t*)&hsd[(size_t)rb * FOUT + col] = *(uint32_t*)&p;
            }
        }
    }
}

// ---------------- GEMM, layers 4-5 (FFMA) ----------------
template <int FIN, int FOUT>
__global__ __launch_bounds__(256) void gemm_small(const float* __restrict__ in,
                                                  const float* __restrict__ W,
                                                  __half* __restrict__ hsd,
                                                  int rowBase0) {
    __shared__ float ws[FIN * FOUT];
    __shared__ float xs[256][9];
    int tid = threadIdx.x;
    for (int i = tid; i < FIN * FOUT; i += 256) ws[i] = W[i];

    int rowBase = rowBase0 + blockIdx.x * 256;
    int row = rowBase + tid;
    float acc[FOUT];
#pragma unroll
    for (int j = 0; j < FOUT; j++) acc[j] = 0.0f;

    for (int k0 = 0; k0 < FIN; k0 += 8) {
#pragma unroll
        for (int i = 0; i < 8; i++) {
            int idx = tid + i * 256;
            int r = idx >> 3, c = idx & 7;
            int gr = rowBase + r;
            xs[r][c] = (gr < NN) ? in[(size_t)gr * FIN + k0 + c] : 0.0f;
        }
        __syncthreads();
#pragma unroll
        for (int k = 0; k < 8; k++) {
            float xv = xs[tid][k];
            const float* wrow = &ws[(k0 + k) * FOUT];
#pragma unroll
            for (int j = 0; j < FOUT; j++)
                acc[j] = fmaf(xv, wrow[j], acc[j]);
        }
        __syncthreads();
    }

    if (row < NN) {
        float dv = g_dinv[row];
#pragma unroll
        for (int j = 0; j < FOUT; j += 8) {
            __half2 ph[4];
#pragma unroll
            for (int q = 0; q < 4; q++)
                ph[q] = __floats2half2_rn(acc[j + 2 * q] * dv,
                                          acc[j + 2 * q + 1] * dv);
            *(uint4*)&hsd[(size_t)row * FOUT + j] = *(uint4*)ph;
        }
    }
}

// ---- aggregate layer 1: raw fp16 h (g_hsA), per-edge dinv; fp16 act ----
__global__ __launch_bounds__(256) void aggregate1(const float* __restrict__ bias,
                                                  int base) {
    constexpr int F = 128;
    int warp = (blockIdx.x * 256 + threadIdx.x) >> 5;
    int lane = threadIdx.x & 31;
    int node = base + warp * 2 + (lane >> 4);
    int c8 = (lane & 15) * 8;
    if (node >= NN) return;

    float dvn = g_dinv[node];
    int beg = g_rowptr[node];
    int end = g_rowptr[node + 1];

    float a[8];
    {
        uint4 raw = *(const uint4*)&g_hsA[(size_t)node * F + c8];
        const __half2* hp = (const __half2*)&raw;
#pragma unroll
        for (int q = 0; q < 4; q++) {
            float2 f = __half22float2(hp[q]);
            a[2 * q]     = dvn * f.x;
            a[2 * q + 1] = dvn * f.y;
        }
    }

    int e = beg;
    for (; e + 1 < end; e += 2) {
        int s0 = g_col[e];
        int s1 = g_col[e + 1];
        float d0 = g_dinv[s0];
        float d1 = g_dinv[s1];
        uint4 r0 = *(const uint4*)&g_hsA[(size_t)s0 * F + c8];
        uint4 r1 = *(const uint4*)&g_hsA[(size_t)s1 * F + c8];
        const __half2* h0 = (const __half2*)&r0;
        const __half2* h1 = (const __half2*)&r1;
#pragma unroll
        for (int q = 0; q < 4; q++) {
            float2 f0 = __half22float2(h0[q]);
            float2 f1 = __half22float2(h1[q]);
            a[2 * q]     = fmaf(d0, f0.x, fmaf(d1, f1.x, a[2 * q]));
            a[2 * q + 1] = fmaf(d0, f0.y, fmaf(d1, f1.y, a[2 * q + 1]));
        }
    }
    if (e < end) {
        int s = g_col[e];
        float ds = g_dinv[s];
        uint4 r = *(const uint4*)&g_hsA[(size_t)s * F + c8];
        const __half2* h = (const __half2*)&r;
#pragma unroll
        for (int q = 0; q < 4; q++) {
            float2 f = __half22float2(h[q]);
            a[2 * q]     = fmaf(ds, f.x, a[2 * q]);
            a[2 * q + 1] = fmaf(ds, f.y, a[2 * q + 1]);
        }
    }

    __half hh[8];
#pragma unroll
    for (int q = 0; q < 8; q++) {
        float b = bias[c8 + q];
        hh[q] = __float2half_rn(fmaxf(fmaf(dvn, a[q], b), 0.0f));
    }
    *(uint4*)&g_ahA[(size_t)node * F + c8] = *(uint4*)hh;
}

// ---- aggregate layer 2 (F=64, hs in g_hsB pre-scaled): fp16 act out ----
__global__ __launch_bounds__(256) void agg_split64(const float* __restrict__ bias,
                                                   int base) {
    constexpr int F = 64;
    int warp = (blockIdx.x * 256 + threadIdx.x) >> 5;
    int lane = threadIdx.x & 31;
    int node = base + warp * 4 + lane / 8;
    int c8 = (lane % 8) * 8;
    if (node >= NN) return;

    float dvn = g_dinv[node];
    int beg = g_rowptr[node];
    int end = g_rowptr[node + 1];

    float a[8];
    {
        uint4 raw = *(const uint4*)&g_hsB[(size_t)node * F + c8];
        const __half2* hp = (const __half2*)&raw;
#pragma unroll
        for (int q = 0; q < 4; q++) {
            float2 f = __half22float2(hp[q]);
            a[2 * q] = f.x;
            a[2 * q + 1] = f.y;
        }
    }
    int e = beg;
    for (; e + 1 < end; e += 2) {
        int s0 = g_col[e];
        int s1 = g_col[e + 1];
        uint4 r0 = *(const uint4*)&g_hsB[(size_t)s0 * F + c8];
        uint4 r1 = *(const uint4*)&g_hsB[(size_t)s1 * F + c8];
        const __half2* h0 = (const __half2*)&r0;
        const __half2* h1 = (const __half2*)&r1;
#pragma unroll
        for (int q = 0; q < 4; q++) {
            float2 f0 = __half22float2(h0[q]);
            float2 f1 = __half22float2(h1[q]);
            a[2 * q]     += f0.x + f1.x;
            a[2 * q + 1] += f0.y + f1.y;
        }
    }
    if (e < end) {
        int s = g_col[e];
        uint4 r = *(const uint4*)&g_hsB[(size_t)s * F + c8];
        const __half2* h = (const __half2*)&r;
#pragma unroll
        for (int q = 0; q < 4; q++) {
            float2 f = __half22float2(h[q]);
            a[2 * q]     += f.x;
            a[2 * q + 1] += f.y;
        }
    }

    __half hh[8];
#pragma unroll
    for (int q = 0; q < 8; q++) {
        float b = bias[c8 + q];
        hh[q] = __float2half_rn(fmaxf(fmaf(dvn, a[q], b), 0.0f));
    }
    *(uint4*)&g_ahB[(size_t)node * F + c8] = *(uint4*)hh;
}

// ---- aggregate layers 3-5: hs pre-scaled; fp32 out ----
template <int F>
__global__ __launch_bounds__(256) void aggregate2(const float* __restrict__ bias,
                                                  float* __restrict__ outp,
                                                  const __half* __restrict__ hs,
                                                  int base) {
    constexpr int L = F / 8;
    constexpr int NPW = 32 / L;
    int warp = (blockIdx.x * 256 + threadIdx.x) >> 5;
    int lane = threadIdx.x & 31;
    int node = base + warp * NPW + lane / L;
    int c8 = (lane % L) * 8;
    if (node >= NN) return;

    float dvn = g_dinv[node];
    int beg = g_rowptr[node];
    int end = g_rowptr[node + 1];

    float a[8];
    {
        uint4 raw = *(const uint4*)&hs[(size_t)node * F + c8];
        const __half2* hp = (const __half2*)&raw;
#pragma unroll
        for (int q = 0; q < 4; q++) {
            float2 f = __half22float2(hp[q]);
            a[2 * q] = f.x;
            a[2 * q + 1] = f.y;
        }
    }
    int e = beg;
    for (; e + 1 < end; e += 2) {
        int s0 = g_col[e];
        int s1 = g_col[e + 1];
        uint4 r0 = *(const uint4*)&hs[(size_t)s0 * F + c8];
        uint4 r1 = *(const uint4*)&hs[(size_t)s1 * F + c8];
        const __half2* h0 = (const __half2*)&r0;
        const __half2* h1 = (const __half2*)&r1;
#pragma unroll
        for (int q = 0; q < 4; q++) {
            float2 f0 = __half22float2(h0[q]);
            float2 f1 = __half22float2(h1[q]);
            a[2 * q]     += f0.x + f1.x;
            a[2 * q + 1] += f0.y + f1.y;
        }
    }
    if (e < end) {
        int s = g_col[e];
        uint4 r = *(const uint4*)&hs[(size_t)s * F + c8];
        const __half2* h = (const __half2*)&r;
#pragma unroll
        for (int q = 0; q < 4; q++) {
            float2 f = __half22float2(h[q]);
            a[2 * q]     += f.x;
            a[2 * q + 1] += f.y;
        }
    }

    float4 b0 = *(const float4*)&bias[c8];
    float4 b1 = *(const float4*)&bias[c8 + 4];
    float4 o0, o1;
    o0.x = fmaxf(fmaf(dvn, a[0], b0.x), 0.0f);
    o0.y = fmaxf(fmaf(dvn, a[1], b0.y), 0.0f);
    o0.z = fmaxf(fmaf(dvn, a[2], b0.z), 0.0f);
    o0.w = fmaxf(fmaf(dvn, a[3], b0.w), 0.0f);
    o1.x = fmaxf(fmaf(dvn, a[4], b1.x), 0.0f);
    o1.y = fmaxf(fmaf(dvn, a[5], b1.y), 0.0f);
    o1.z = fmaxf(fmaf(dvn, a[6], b1.z), 0.0f);
    o1.w = fmaxf(fmaf(dvn, a[7], b1.w), 0.0f);
    *(float4*)&outp[(size_t)node * F + c8]     = o0;
    *(float4*)&outp[(size_t)node * F + c8 + 4] = o1;
}

static inline int blocks_for(int count, int npb) {
    return (count + npb - 1) / npb;
}

// ---------------- launch ----------------
extern "C" void kernel_launch(void* const* d_in, const int* in_sizes, int n_in,
                              void* d_out, int out_size) {
    const float* x  = (const float*)d_in[0];
    const void*  ei = d_in[1];
    const float* W1 = (const float*)d_in[2];
    const float* b1 = (const float*)d_in[3];
    const float* W2 = (const float*)d_in[4];
    const float* b2 = (const float*)d_in[5];
    const float* W3 = (const float*)d_in[6];
    const float* b3 = (const float*)d_in[7];
    const float* W4 = (const float*)d_in[8];
    const float* b4 = (const float*)d_in[9];
    const float* W5 = (const float*)d_in[10];
    const float* b5 = (const float*)d_in[11];
    float* out = (float*)d_out;

    constexpr int SM1 = 3 * 128 * STR * 2;                    // 104448
    constexpr int SM2 = (128 + 2 * 64) * 136 * 2;             //  69632
    constexpr int SM3 = (128 + 2 * 32) * 72 * 2;              //  27648

    static float* act = nullptr;
    static __half *ahA, *ahB, *hsA, *hsB;
    static cudaStream_t s1 = nullptr;
    static cudaEvent_t evF, evPrep, evG1, evA1h1, evG2, evA2h1, evG3, evA3h1;
    if (!act) {
        cudaGetSymbolAddress((void**)&act, g_act);
        cudaGetSymbolAddress((void**)&ahA, g_ahA);
        cudaGetSymbolAddress((void**)&ahB, g_ahB);
        cudaGetSymbolAddress((void**)&hsA, g_hsA);
        cudaGetSymbolAddress((void**)&hsB, g_hsB);
        cudaStreamCreateWithFlags(&s1, cudaStreamNonBlocking);
        cudaEventCreateWithFlags(&evF,    cudaEventDisableTiming);
        cudaEventCreateWithFlags(&evPrep, cudaEventDisableTiming);
        cudaEventCreateWithFlags(&evG1,   cudaEventDisableTiming);
        cudaEventCreateWithFlags(&evA1h1, cudaEventDisableTiming);
        cudaEventCreateWithFlags(&evG2,   cudaEventDisableTiming);
        cudaEventCreateWithFlags(&evA2h1, cudaEventDisableTiming);
        cudaEventCreateWithFlags(&evG3,   cudaEventDisableTiming);
        cudaEventCreateWithFlags(&evA3h1, cudaEventDisableTiming);
        cudaFuncSetAttribute(gemm_mma1, cudaFuncAttributeMaxDynamicSharedMemorySize, SM1);
        cudaFuncSetAttribute(gemm_mmaT<128, 64>, cudaFuncAttributeMaxDynamicSharedMemorySize, SM2);
        cudaFuncSetAttribute(gemm_mmaT<64, 32>, cudaFuncAttributeMaxDynamicSharedMemorySize, SM3);
    }

    const int H0 = NSPLIT, H1 = NN - NSPLIT;
    int nb = (NN + 255) / 256;
    int eb = (NE + 255) / 256;

    // fork: CSR build on s1; W split + layer-1 GEMM on s0
    cudaEventRecord(evF, 0);
    cudaStreamWaitEvent(s1, evF, 0);

    k_sniff_zero   <<<nb, 256, 0, s1>>>((const unsigned int*)ei);
    k_deg          <<<eb, 256, 0, s1>>>(ei);
    k_scan1        <<<NBLK, SCAN_B, 0, s1>>>();
    k_scan2        <<<1, 512, 0, s1>>>();
    k_finalize_csr <<<nb, 256, 0, s1>>>();
    k_fill         <<<eb, 256, 0, s1>>>(ei);
    cudaEventRecord(evPrep, s1);

    k_wsplit1 <<<64, 256>>>(W1);
    k_wsplit2 <<<32, 256>>>(W2);
    k_wsplit3 <<<8, 256>>>(W3);
    gemm_mma1 <<<(NN + 127) / 128, 256, SM1>>>(x);
    cudaEventRecord(evG1, 0);

    // ---- layer 1 aggregate, split halves ----
    cudaStreamWaitEvent(s1, evG1, 0);
    aggregate1 <<<blocks_for(H1, 16), 256, 0, s1>>>(b1, NSPLIT);
    cudaEventRecord(evA1h1, s1);

    cudaStreamWaitEvent(0, evPrep, 0);
    aggregate1 <<<blocks_for(H0, 16), 256>>>(b1, 0);

    // ---- layer 2 gemm (mma), pipelined with A1 half1 ----
    gemm_mmaT<128, 64> <<<H0 / 128, 256, SM2>>>(ahA, hsB, 0);
    cudaStreamWaitEvent(0, evA1h1, 0);
    gemm_mmaT<128, 64> <<<blocks_for(H1, 128), 256, SM2>>>(ahA, hsB, NSPLIT);
    cudaEventRecord(evG2, 0);

    // ---- layer 2 aggregate (fp16 act out), halves ----
    cudaStreamWaitEvent(s1, evG2, 0);
    agg_split64 <<<blocks_for(H1, 32), 256, 0, s1>>>(b2, NSPLIT);
    cudaEventRecord(evA2h1, s1);
    agg_split64 <<<blocks_for(H0, 32), 256>>>(b2, 0);

    // ---- layer 3 gemm (mma), pipelined ----
    gemm_mmaT<64, 32> <<<H0 / 128, 256, SM3>>>(ahB, hsA, 0);
    cudaStreamWaitEvent(0, evA2h1, 0);
    gemm_mmaT<64, 32> <<<blocks_for(H1, 128), 256, SM3>>>(ahB, hsA, NSPLIT);
    cudaEventRecord(evG3, 0);

    // ---- layer 3 aggregate (fp32 act out), halves ----
    cudaStreamWaitEvent(s1, evG3, 0);
    aggregate2<32> <<<blocks_for(H1, 64), 256, 0, s1>>>(b3, act, hsA, NSPLIT);
    cudaEventRecord(evA3h1, s1);
    aggregate2<32> <<<blocks_for(H0, 64), 256>>>(b3, act, hsA, 0);

    // ---- layer 4 gemm (FFMA), pipelined ----
    gemm_small<32, 16> <<<H0 / 256, 256>>>(act, W4, hsB, 0);
    cudaStreamWaitEvent(0, evA3h1, 0);
    gemm_small<32, 16> <<<blocks_for(H1, 256), 256>>>(act, W4, hsB, NSPLIT);

    // ---- tail, sequential on s0 ----
    aggregate2<16> <<<blocks_for(NN, 128), 256>>>(b4, act, hsB, 0);
    gemm_small<16, 8> <<<nb, 256>>>(act, W5, hsA, 0);
    aggregate2<8> <<<blocks_for(NN, 256), 256>>>(b5, out, hsA, 0);
}